// round 1
// baseline (speedup 1.0000x reference)
#include <cuda_runtime.h>
#include <cstdint>
#include <cstddef>

// Problem constants
#define B_WIN  200
#define S_DIM  14
#define HW     196           // 14*14
#define C_DIM  768
#define NH     12
#define HD     64
#define M_TOK  (B_WIN * HW)  // 39200
#define QKV_N  (3 * C_DIM)   // 2304

// Scratch (device globals: allocation-free per harness rules)
__device__ float g_qkv[(size_t)M_TOK * QKV_N];   // (B*HW, 2304)
__device__ float g_ctx[(size_t)M_TOK * C_DIM];   // (B*HW, 768) head-merged context

// ---------------------------------------------------------------------------
// SGEMM: C = A(MxK) * B(KxN) + bias(N), row-major. BM=BN=128, BK=8, 8x8/thread.
// ---------------------------------------------------------------------------
__global__ __launch_bounds__(256, 2)
void sgemm_bias_kernel(const float* __restrict__ A, const float* __restrict__ B,
                       const float* __restrict__ bias, float* __restrict__ C,
                       int M, int N, int K) {
    __shared__ float As[8][128];   // transposed A tile
    __shared__ float Bs[8][128];

    const int tid = threadIdx.x;
    const int tx = tid & 15;
    const int ty = tid >> 4;
    const int m0 = blockIdx.y * 128;
    const int n0 = blockIdx.x * 128;

    const int aRow = tid >> 1;          // 0..127
    const int aCol = (tid & 1) * 4;     // 0 or 4
    const int bRow = tid >> 5;          // 0..7
    const int bCol = (tid & 31) * 4;    // 0..124

    float acc[8][8];
#pragma unroll
    for (int i = 0; i < 8; i++)
#pragma unroll
        for (int j = 0; j < 8; j++) acc[i][j] = 0.f;

    for (int k0 = 0; k0 < K; k0 += 8) {
        float4 av = make_float4(0.f, 0.f, 0.f, 0.f);
        if (m0 + aRow < M)
            av = *(const float4*)(A + (size_t)(m0 + aRow) * K + k0 + aCol);
        As[aCol + 0][aRow] = av.x;
        As[aCol + 1][aRow] = av.y;
        As[aCol + 2][aRow] = av.z;
        As[aCol + 3][aRow] = av.w;

        float4 bv = *(const float4*)(B + (size_t)(k0 + bRow) * N + n0 + bCol);
        *(float4*)&Bs[bRow][bCol] = bv;
        __syncthreads();

#pragma unroll
        for (int kk = 0; kk < 8; kk++) {
            float af[8], bf[8];
            *(float4*)&af[0] = *(const float4*)&As[kk][ty * 4];
            *(float4*)&af[4] = *(const float4*)&As[kk][64 + ty * 4];
            *(float4*)&bf[0] = *(const float4*)&Bs[kk][tx * 4];
            *(float4*)&bf[4] = *(const float4*)&Bs[kk][64 + tx * 4];
#pragma unroll
            for (int i = 0; i < 8; i++)
#pragma unroll
                for (int j = 0; j < 8; j++)
                    acc[i][j] += af[i] * bf[j];
        }
        __syncthreads();
    }

    // epilogue: rows {ty*4+i, 64+ty*4+i}, cols {tx*4+j, 64+tx*4+j}
#pragma unroll
    for (int i = 0; i < 8; i++) {
        int m = m0 + ((i < 4) ? (ty * 4 + i) : (64 + ty * 4 + i - 4));
        if (m >= M) continue;
#pragma unroll
        for (int jh = 0; jh < 2; jh++) {
            int n = n0 + jh * 64 + tx * 4;
            float4 r;
            r.x = acc[i][jh * 4 + 0] + bias[n + 0];
            r.y = acc[i][jh * 4 + 1] + bias[n + 1];
            r.z = acc[i][jh * 4 + 2] + bias[n + 2];
            r.w = acc[i][jh * 4 + 3] + bias[n + 3];
            *(float4*)(C + (size_t)m * N + n) = r;
        }
    }
}

// ---------------------------------------------------------------------------
// Fused attention: one CTA per (window b, head h). 256 threads.
// SMEM: kT[64][200], v[196][64], qT[64][65], attn[64][200], relh/relw[64][14]
// ---------------------------------------------------------------------------
#define ATTN_SMEM_FLOATS (64*200 + 196*64 + 64*65 + 64*200 + 64*14 + 64*14)
#define ATTN_SMEM_BYTES  (ATTN_SMEM_FLOATS * 4)

__global__ __launch_bounds__(256)
void attn_kernel(const float* __restrict__ qkv,
                 const float* __restrict__ rph,
                 const float* __restrict__ rpw,
                 float* __restrict__ ctx) {
    extern __shared__ float sm[];
    float* kT  = sm;                  // [64][200]  (K transposed, padded)
    float* vS  = kT  + 64 * 200;      // [196][64]
    float* qT  = vS  + 196 * 64;      // [64][65]   (q-block transposed)
    float* at  = qT  + 64 * 65;       // [64][200]  logits/probs
    float* rlh = at  + 64 * 200;      // [64][14]
    float* rlw = rlh + 64 * 14;       // [64][14]

    const int bh = blockIdx.x;
    const int b = bh / NH;
    const int h = bh % NH;
    const int tid  = threadIdx.x;
    const int tx   = tid & 15;
    const int ty   = tid >> 4;
    const int warp = tid >> 5;
    const int lane = tid & 31;
    const float scale = 0.125f;   // 64^-0.5

    const float* qkv_b = qkv + (size_t)b * HW * QKV_N;

    // Stage K (transposed) and V once
    for (int idx = tid; idx < HW * HD; idx += 256) {
        int s = idx >> 6;
        int d = idx & 63;
        const float* base = qkv_b + (size_t)s * QKV_N + h * HD + d;
        kT[d * 200 + s] = base[C_DIM];       // k
        vS[idx]         = base[2 * C_DIM];   // v
    }

    for (int qb = 0; qb < 4; qb++) {
        const int qbase = qb * 64;
        __syncthreads();  // previous iter done with qT/at; first iter: kT/vS in flight, synced below

        // load q block transposed
        for (int idx = tid; idx < 64 * HD; idx += 256) {
            int ql = idx >> 6;
            int d  = idx & 63;
            int s  = qbase + ql;
            float v = 0.f;
            if (s < HW) v = qkv_b[(size_t)s * QKV_N + h * HD + d];
            qT[d * 65 + ql] = v;
        }
        __syncthreads();

        // decomposed rel-pos tables: rlh[q][kh] = q . rel_pos_h[hq-kh+13]
        for (int idx = tid; idx < 64 * S_DIM; idx += 256) {
            int ql = idx / S_DIM;
            int kk = idx % S_DIM;
            int s  = qbase + ql;
            float sh = 0.f, sw = 0.f;
            if (s < HW) {
                int hq = s / S_DIM;
                int wq = s % S_DIM;
                const float* ph = rph + (hq - kk + S_DIM - 1) * HD;
                const float* pw = rpw + (wq - kk + S_DIM - 1) * HD;
#pragma unroll 8
                for (int d = 0; d < HD; d++) {
                    float qv = qT[d * 65 + ql];
                    sh += qv * ph[d];
                    sw += qv * pw[d];
                }
            }
            rlh[ql * S_DIM + kk] = sh;
            rlw[ql * S_DIM + kk] = sw;
        }
        __syncthreads();

        // logits: at[q][k] = scale*(q.k) + rlh[q][k/14] + rlw[q][k%14]
        for (int kb = 0; kb < 4; kb++) {
            const int kbase = kb * 64;
            float acc[4][4];
#pragma unroll
            for (int i = 0; i < 4; i++)
#pragma unroll
                for (int j = 0; j < 4; j++) acc[i][j] = 0.f;

#pragma unroll 8
            for (int d = 0; d < HD; d++) {
                float qf[4];
#pragma unroll
                for (int i = 0; i < 4; i++) qf[i] = qT[d * 65 + ty * 4 + i];
                float4 kv = *(const float4*)&kT[d * 200 + kbase + tx * 4];
                float kf[4] = {kv.x, kv.y, kv.z, kv.w};
#pragma unroll
                for (int i = 0; i < 4; i++)
#pragma unroll
                    for (int j = 0; j < 4; j++)
                        acc[i][j] += qf[i] * kf[j];
            }
#pragma unroll
            for (int i = 0; i < 4; i++) {
                int r = ty * 4 + i;
#pragma unroll
                for (int j = 0; j < 4; j++) {
                    int kq = kbase + tx * 4 + j;
                    if (kq < HW)
                        at[r * 200 + kq] = acc[i][j] * scale
                                         + rlh[r * S_DIM + kq / S_DIM]
                                         + rlw[r * S_DIM + kq % S_DIM];
                }
            }
        }
        __syncthreads();

        // softmax per row (8 warps x 8 rows)
        for (int r = warp; r < 64; r += 8) {
            float mx = -1e30f;
            for (int k = lane; k < HW; k += 32) mx = fmaxf(mx, at[r * 200 + k]);
#pragma unroll
            for (int o = 16; o > 0; o >>= 1) mx = fmaxf(mx, __shfl_xor_sync(0xffffffffu, mx, o));
            float sum = 0.f;
            for (int k = lane; k < HW; k += 32) {
                float e = __expf(at[r * 200 + k] - mx);
                at[r * 200 + k] = e;
                sum += e;
            }
#pragma unroll
            for (int o = 16; o > 0; o >>= 1) sum += __shfl_xor_sync(0xffffffffu, sum, o);
            float inv = 1.0f / sum;
            for (int k = lane; k < HW; k += 32) at[r * 200 + k] *= inv;
        }
        __syncthreads();

        // out = attn @ V : thread covers rows ty*4..+3, cols tx*4..+3
        {
            float4 o0 = make_float4(0,0,0,0), o1 = o0, o2 = o0, o3 = o0;
#pragma unroll 4
            for (int k = 0; k < HW; k++) {
                float4 vv = *(const float4*)&vS[k * 64 + tx * 4];
                float a0 = at[(ty * 4 + 0) * 200 + k];
                float a1 = at[(ty * 4 + 1) * 200 + k];
                float a2 = at[(ty * 4 + 2) * 200 + k];
                float a3 = at[(ty * 4 + 3) * 200 + k];
                o0.x += a0 * vv.x; o0.y += a0 * vv.y; o0.z += a0 * vv.z; o0.w += a0 * vv.w;
                o1.x += a1 * vv.x; o1.y += a1 * vv.y; o1.z += a1 * vv.z; o1.w += a1 * vv.w;
                o2.x += a2 * vv.x; o2.y += a2 * vv.y; o2.z += a2 * vv.z; o2.w += a2 * vv.w;
                o3.x += a3 * vv.x; o3.y += a3 * vv.y; o3.z += a3 * vv.z; o3.w += a3 * vv.w;
            }
            float4 ov[4] = {o0, o1, o2, o3};
#pragma unroll
            for (int i = 0; i < 4; i++) {
                int s = qbase + ty * 4 + i;
                if (s < HW) {
                    float* dst = ctx + (size_t)(b * HW + s) * C_DIM + h * HD + tx * 4;
                    *(float4*)dst = ov[i];
                }
            }
        }
    }
}

// ---------------------------------------------------------------------------
extern "C" void kernel_launch(void* const* d_in, const int* in_sizes, int n_in,
                              void* d_out, int out_size) {
    const float* x      = (const float*)d_in[0];
    const float* w_qkv  = (const float*)d_in[1];
    const float* b_qkv  = (const float*)d_in[2];
    const float* w_proj = (const float*)d_in[3];
    const float* b_proj = (const float*)d_in[4];
    const float* rph    = (const float*)d_in[5];
    const float* rpw    = (const float*)d_in[6];
    float* out = (float*)d_out;

    float *qkv_ptr = nullptr, *ctx_ptr = nullptr;
    cudaGetSymbolAddress((void**)&qkv_ptr, g_qkv);
    cudaGetSymbolAddress((void**)&ctx_ptr, g_ctx);

    static bool attr_set = false;
    if (!attr_set) {
        cudaFuncSetAttribute(attn_kernel,
                             cudaFuncAttributeMaxDynamicSharedMemorySize,
                             ATTN_SMEM_BYTES);
        attr_set = true;
    }

    // 1) QKV projection: (39200 x 768) @ (768 x 2304) + b_qkv
    {
        dim3 grid(QKV_N / 128, (M_TOK + 127) / 128);  // 18 x 307
        sgemm_bias_kernel<<<grid, 256>>>(x, w_qkv, b_qkv, qkv_ptr,
                                         M_TOK, QKV_N, C_DIM);
    }

    // 2) Fused attention per (window, head)
    attn_kernel<<<B_WIN * NH, 256, ATTN_SMEM_BYTES>>>(qkv_ptr, rph, rpw, ctx_ptr);

    // 3) Output projection: (39200 x 768) @ (768 x 768) + b_proj
    {
        dim3 grid(C_DIM / 128, (M_TOK + 127) / 128);  // 6 x 307
        sgemm_bias_kernel<<<grid, 256>>>(ctx_ptr, w_proj, b_proj, out,
                                         M_TOK, C_DIM, C_DIM);
    }
}

// round 2
// speedup vs baseline: 1.5107x; 1.5107x over previous
#include <cuda_runtime.h>
#include <cstdint>
#include <cstddef>

// Problem constants
#define B_WIN  200
#define S_DIM  14
#define HW     196           // 14*14
#define C_DIM  768
#define NH     12
#define HD     64
#define M_TOK  (B_WIN * HW)  // 39200
#define QKV_N  (3 * C_DIM)   // 2304

// Scratch (device globals: allocation-free per harness rules)
__device__ float g_qkv[(size_t)M_TOK * QKV_N];   // (B*HW, 2304)
__device__ float g_ctx[(size_t)M_TOK * C_DIM];   // (B*HW, 768) head-merged context

// ---------------------------------------------------------------------------
// tf32 helpers
// ---------------------------------------------------------------------------
__device__ __forceinline__ float f2tf32(float x) {
    uint32_t r;
    asm("cvt.rna.tf32.f32 %0, %1;" : "=r"(r) : "f"(x));
    return __uint_as_float(r);
}

__device__ __forceinline__ void mma_tf32(float* c, const uint32_t* a, const uint32_t* b) {
    asm volatile(
        "mma.sync.aligned.m16n8k8.row.col.f32.tf32.tf32.f32 "
        "{%0,%1,%2,%3}, {%4,%5,%6,%7}, {%8,%9}, {%0,%1,%2,%3};"
        : "+f"(c[0]), "+f"(c[1]), "+f"(c[2]), "+f"(c[3])
        : "r"(a[0]), "r"(a[1]), "r"(a[2]), "r"(a[3]),
          "r"(b[0]), "r"(b[1]));
}

// ---------------------------------------------------------------------------
// Tensor-core tf32 GEMM: C = A(MxK) @ B(KxN) + bias(N), all row-major fp32.
// BM=BN=128, BK=32. 256 threads = 8 warps in 4(m) x 2(n); warp tile 32x64.
// Per warp: 2 m16-tiles x 8 n8-tiles of m16n8k8 mma.
// ---------------------------------------------------------------------------
#define BM 128
#define BN 128
#define BK 32

__global__ __launch_bounds__(256, 2)
void gemm_tf32_bias(const float* __restrict__ A, const float* __restrict__ B,
                    const float* __restrict__ bias, float* __restrict__ C,
                    int M, int N, int K) {
    __shared__ float As[BM][BK + 4];   // stride 36: A-frag banks 4g+tig (conflict-free)
    __shared__ float Bs[BK][BN + 8];   // stride 136: B-frag banks 8t+g (conflict-free)

    const int tid  = threadIdx.x;
    const int warp = tid >> 5;
    const int lane = tid & 31;
    const int wm   = warp >> 1;        // 0..3
    const int wn   = warp & 1;         // 0..1
    const int g    = lane >> 2;        // groupID 0..7
    const int tig  = lane & 3;         // threadID in group 0..3
    const int m0   = blockIdx.y * BM;
    const int n0   = blockIdx.x * BN;

    float acc[2][8][4];
#pragma unroll
    for (int mt = 0; mt < 2; mt++)
#pragma unroll
        for (int nt = 0; nt < 8; nt++)
#pragma unroll
            for (int i = 0; i < 4; i++) acc[mt][nt][i] = 0.f;

    for (int kt = 0; kt < K; kt += BK) {
        // Stage A tile (guard rows), convert to tf32
#pragma unroll
        for (int i = 0; i < 4; i++) {
            int pos = tid + i * 256;       // 0..1023 float4 slots
            int r   = pos >> 3;            // 0..127
            int cv  = (pos & 7) * 4;       // 0..28
            float4 v = make_float4(0.f, 0.f, 0.f, 0.f);
            if (m0 + r < M)
                v = *(const float4*)(A + (size_t)(m0 + r) * K + kt + cv);
            As[r][cv + 0] = f2tf32(v.x);
            As[r][cv + 1] = f2tf32(v.y);
            As[r][cv + 2] = f2tf32(v.z);
            As[r][cv + 3] = f2tf32(v.w);
        }
        // Stage B tile (K multiple of 32, N multiple of 128: no guards)
#pragma unroll
        for (int i = 0; i < 4; i++) {
            int pos = tid + i * 256;
            int r   = pos >> 5;            // 0..31
            int cv  = (pos & 31) * 4;      // 0..124
            float4 v = *(const float4*)(B + (size_t)(kt + r) * N + n0 + cv);
            Bs[r][cv + 0] = f2tf32(v.x);
            Bs[r][cv + 1] = f2tf32(v.y);
            Bs[r][cv + 2] = f2tf32(v.z);
            Bs[r][cv + 3] = f2tf32(v.w);
        }
        __syncthreads();

#pragma unroll
        for (int ks = 0; ks < 4; ks++) {
            const int kb = ks * 8;
            uint32_t a[2][4];
#pragma unroll
            for (int mt = 0; mt < 2; mt++) {
                const int row = wm * 32 + mt * 16;
                a[mt][0] = __float_as_uint(As[row + g    ][kb + tig    ]);
                a[mt][1] = __float_as_uint(As[row + g + 8][kb + tig    ]);
                a[mt][2] = __float_as_uint(As[row + g    ][kb + tig + 4]);
                a[mt][3] = __float_as_uint(As[row + g + 8][kb + tig + 4]);
            }
            uint32_t b[8][2];
#pragma unroll
            for (int nt = 0; nt < 8; nt++) {
                const int col = wn * 64 + nt * 8 + g;
                b[nt][0] = __float_as_uint(Bs[kb + tig    ][col]);
                b[nt][1] = __float_as_uint(Bs[kb + tig + 4][col]);
            }
#pragma unroll
            for (int mt = 0; mt < 2; mt++)
#pragma unroll
                for (int nt = 0; nt < 8; nt++)
                    mma_tf32(acc[mt][nt], a[mt], b[nt]);
        }
        __syncthreads();
    }

    // Epilogue: c0/c1 -> (row, 2tig/2tig+1), c2/c3 -> (row+8, ...)
#pragma unroll
    for (int mt = 0; mt < 2; mt++) {
        const int row0 = m0 + wm * 32 + mt * 16 + g;
#pragma unroll
        for (int nt = 0; nt < 8; nt++) {
            const int col = n0 + wn * 64 + nt * 8 + tig * 2;
            const float2 bv = *(const float2*)(bias + col);
            if (row0 < M) {
                float2 r0 = make_float2(acc[mt][nt][0] + bv.x, acc[mt][nt][1] + bv.y);
                *(float2*)(C + (size_t)row0 * N + col) = r0;
            }
            if (row0 + 8 < M) {
                float2 r1 = make_float2(acc[mt][nt][2] + bv.x, acc[mt][nt][3] + bv.y);
                *(float2*)(C + (size_t)(row0 + 8) * N + col) = r1;
            }
        }
    }
}

// ---------------------------------------------------------------------------
// Fused attention: one CTA per (window b, head h). 256 threads. (unchanged)
// ---------------------------------------------------------------------------
#define ATTN_SMEM_FLOATS (64*200 + 196*64 + 64*65 + 64*200 + 64*14 + 64*14)
#define ATTN_SMEM_BYTES  (ATTN_SMEM_FLOATS * 4)

__global__ __launch_bounds__(256)
void attn_kernel(const float* __restrict__ qkv,
                 const float* __restrict__ rph,
                 const float* __restrict__ rpw,
                 float* __restrict__ ctx) {
    extern __shared__ float sm[];
    float* kT  = sm;                  // [64][200]
    float* vS  = kT  + 64 * 200;      // [196][64]
    float* qT  = vS  + 196 * 64;      // [64][65]
    float* at  = qT  + 64 * 65;       // [64][200]
    float* rlh = at  + 64 * 200;      // [64][14]
    float* rlw = rlh + 64 * 14;       // [64][14]

    const int bh = blockIdx.x;
    const int b = bh / NH;
    const int h = bh % NH;
    const int tid  = threadIdx.x;
    const int tx   = tid & 15;
    const int ty   = tid >> 4;
    const int warp = tid >> 5;
    const int lane = tid & 31;
    const float scale = 0.125f;

    const float* qkv_b = qkv + (size_t)b * HW * QKV_N;

    for (int idx = tid; idx < HW * HD; idx += 256) {
        int s = idx >> 6;
        int d = idx & 63;
        const float* base = qkv_b + (size_t)s * QKV_N + h * HD + d;
        kT[d * 200 + s] = base[C_DIM];
        vS[idx]         = base[2 * C_DIM];
    }

    for (int qb = 0; qb < 4; qb++) {
        const int qbase = qb * 64;
        __syncthreads();

        for (int idx = tid; idx < 64 * HD; idx += 256) {
            int ql = idx >> 6;
            int d  = idx & 63;
            int s  = qbase + ql;
            float v = 0.f;
            if (s < HW) v = qkv_b[(size_t)s * QKV_N + h * HD + d];
            qT[d * 65 + ql] = v;
        }
        __syncthreads();

        for (int idx = tid; idx < 64 * S_DIM; idx += 256) {
            int ql = idx / S_DIM;
            int kk = idx % S_DIM;
            int s  = qbase + ql;
            float sh = 0.f, sw = 0.f;
            if (s < HW) {
                int hq = s / S_DIM;
                int wq = s % S_DIM;
                const float* ph = rph + (hq - kk + S_DIM - 1) * HD;
                const float* pw = rpw + (wq - kk + S_DIM - 1) * HD;
#pragma unroll 8
                for (int d = 0; d < HD; d++) {
                    float qv = qT[d * 65 + ql];
                    sh += qv * ph[d];
                    sw += qv * pw[d];
                }
            }
            rlh[ql * S_DIM + kk] = sh;
            rlw[ql * S_DIM + kk] = sw;
        }
        __syncthreads();

        for (int kb = 0; kb < 4; kb++) {
            const int kbase = kb * 64;
            float acc[4][4];
#pragma unroll
            for (int i = 0; i < 4; i++)
#pragma unroll
                for (int j = 0; j < 4; j++) acc[i][j] = 0.f;

#pragma unroll 8
            for (int d = 0; d < HD; d++) {
                float qf[4];
#pragma unroll
                for (int i = 0; i < 4; i++) qf[i] = qT[d * 65 + ty * 4 + i];
                float4 kv = *(const float4*)&kT[d * 200 + kbase + tx * 4];
                float kf[4] = {kv.x, kv.y, kv.z, kv.w};
#pragma unroll
                for (int i = 0; i < 4; i++)
#pragma unroll
                    for (int j = 0; j < 4; j++)
                        acc[i][j] += qf[i] * kf[j];
            }
#pragma unroll
            for (int i = 0; i < 4; i++) {
                int r = ty * 4 + i;
#pragma unroll
                for (int j = 0; j < 4; j++) {
                    int kq = kbase + tx * 4 + j;
                    if (kq < HW)
                        at[r * 200 + kq] = acc[i][j] * scale
                                         + rlh[r * S_DIM + kq / S_DIM]
                                         + rlw[r * S_DIM + kq % S_DIM];
                }
            }
        }
        __syncthreads();

        for (int r = warp; r < 64; r += 8) {
            float mx = -1e30f;
            for (int k = lane; k < HW; k += 32) mx = fmaxf(mx, at[r * 200 + k]);
#pragma unroll
            for (int o = 16; o > 0; o >>= 1) mx = fmaxf(mx, __shfl_xor_sync(0xffffffffu, mx, o));
            float sum = 0.f;
            for (int k = lane; k < HW; k += 32) {
                float e = __expf(at[r * 200 + k] - mx);
                at[r * 200 + k] = e;
                sum += e;
            }
#pragma unroll
            for (int o = 16; o > 0; o >>= 1) sum += __shfl_xor_sync(0xffffffffu, sum, o);
            float inv = 1.0f / sum;
            for (int k = lane; k < HW; k += 32) at[r * 200 + k] *= inv;
        }
        __syncthreads();

        {
            float4 o0 = make_float4(0,0,0,0), o1 = o0, o2 = o0, o3 = o0;
#pragma unroll 4
            for (int k = 0; k < HW; k++) {
                float4 vv = *(const float4*)&vS[k * 64 + tx * 4];
                float a0 = at[(ty * 4 + 0) * 200 + k];
                float a1 = at[(ty * 4 + 1) * 200 + k];
                float a2 = at[(ty * 4 + 2) * 200 + k];
                float a3 = at[(ty * 4 + 3) * 200 + k];
                o0.x += a0 * vv.x; o0.y += a0 * vv.y; o0.z += a0 * vv.z; o0.w += a0 * vv.w;
                o1.x += a1 * vv.x; o1.y += a1 * vv.y; o1.z += a1 * vv.z; o1.w += a1 * vv.w;
                o2.x += a2 * vv.x; o2.y += a2 * vv.y; o2.z += a2 * vv.z; o2.w += a2 * vv.w;
                o3.x += a3 * vv.x; o3.y += a3 * vv.y; o3.z += a3 * vv.z; o3.w += a3 * vv.w;
            }
            float4 ov[4] = {o0, o1, o2, o3};
#pragma unroll
            for (int i = 0; i < 4; i++) {
                int s = qbase + ty * 4 + i;
                if (s < HW) {
                    float* dst = ctx + (size_t)(b * HW + s) * C_DIM + h * HD + tx * 4;
                    *(float4*)dst = ov[i];
                }
            }
        }
    }
}

// ---------------------------------------------------------------------------
extern "C" void kernel_launch(void* const* d_in, const int* in_sizes, int n_in,
                              void* d_out, int out_size) {
    const float* x      = (const float*)d_in[0];
    const float* w_qkv  = (const float*)d_in[1];
    const float* b_qkv  = (const float*)d_in[2];
    const float* w_proj = (const float*)d_in[3];
    const float* b_proj = (const float*)d_in[4];
    const float* rph    = (const float*)d_in[5];
    const float* rpw    = (const float*)d_in[6];
    float* out = (float*)d_out;

    float *qkv_ptr = nullptr, *ctx_ptr = nullptr;
    cudaGetSymbolAddress((void**)&qkv_ptr, g_qkv);
    cudaGetSymbolAddress((void**)&ctx_ptr, g_ctx);

    static bool attr_set = false;
    if (!attr_set) {
        cudaFuncSetAttribute(attn_kernel,
                             cudaFuncAttributeMaxDynamicSharedMemorySize,
                             ATTN_SMEM_BYTES);
        attr_set = true;
    }

    // 1) QKV projection: (39200 x 768) @ (768 x 2304) + b_qkv  [tf32 tensor core]
    {
        dim3 grid(QKV_N / BN, (M_TOK + BM - 1) / BM);  // 18 x 307
        gemm_tf32_bias<<<grid, 256>>>(x, w_qkv, b_qkv, qkv_ptr,
                                      M_TOK, QKV_N, C_DIM);
    }

    // 2) Fused attention per (window, head)  [fp32]
    attn_kernel<<<B_WIN * NH, 256, ATTN_SMEM_BYTES>>>(qkv_ptr, rph, rpw, ctx_ptr);

    // 3) Output projection: (39200 x 768) @ (768 x 768) + b_proj  [tf32 tensor core]
    {
        dim3 grid(C_DIM / BN, (M_TOK + BM - 1) / BM);  // 6 x 307
        gemm_tf32_bias<<<grid, 256>>>(ctx_ptr, w_proj, b_proj, out,
                                      M_TOK, C_DIM, C_DIM);
    }
}

// round 3
// speedup vs baseline: 1.7040x; 1.1280x over previous
#include <cuda_runtime.h>
#include <cstdint>
#include <cstddef>

// Problem constants
#define B_WIN  200
#define S_DIM  14
#define HW     196           // 14*14
#define C_DIM  768
#define NH     12
#define HD     64
#define M_TOK  (B_WIN * HW)  // 39200
#define QKV_N  (3 * C_DIM)   // 2304

// Scratch (device globals: allocation-free per harness rules)
__device__ float g_qkv[(size_t)M_TOK * QKV_N];   // (B*HW, 2304)
__device__ float g_ctx[(size_t)M_TOK * C_DIM];   // (B*HW, 768) head-merged context

// ---------------------------------------------------------------------------
// tf32 helpers
// ---------------------------------------------------------------------------
__device__ __forceinline__ float f2tf32(float x) {
    uint32_t r;
    asm("cvt.rna.tf32.f32 %0, %1;" : "=r"(r) : "f"(x));
    return __uint_as_float(r);
}

__device__ __forceinline__ void split_tf32(float x, uint32_t& hi, uint32_t& lo) {
    float h = f2tf32(x);
    float l = f2tf32(x - h);
    hi = __float_as_uint(h);
    lo = __float_as_uint(l);
}

__device__ __forceinline__ void mma_tf32(float* c, const uint32_t* a, const uint32_t* b) {
    asm volatile(
        "mma.sync.aligned.m16n8k8.row.col.f32.tf32.tf32.f32 "
        "{%0,%1,%2,%3}, {%4,%5,%6,%7}, {%8,%9}, {%0,%1,%2,%3};"
        : "+f"(c[0]), "+f"(c[1]), "+f"(c[2]), "+f"(c[3])
        : "r"(a[0]), "r"(a[1]), "r"(a[2]), "r"(a[3]),
          "r"(b[0]), "r"(b[1]));
}

// ---------------------------------------------------------------------------
// Tensor-core tf32 GEMM: C = A(MxK) @ B(KxN) + bias(N), all row-major fp32.
// (unchanged from R2)
// ---------------------------------------------------------------------------
#define BM 128
#define BN 128
#define BK 32

__global__ __launch_bounds__(256, 2)
void gemm_tf32_bias(const float* __restrict__ A, const float* __restrict__ B,
                    const float* __restrict__ bias, float* __restrict__ C,
                    int M, int N, int K) {
    __shared__ float As[BM][BK + 4];
    __shared__ float Bs[BK][BN + 8];

    const int tid  = threadIdx.x;
    const int warp = tid >> 5;
    const int lane = tid & 31;
    const int wm   = warp >> 1;
    const int wn   = warp & 1;
    const int g    = lane >> 2;
    const int tig  = lane & 3;
    const int m0   = blockIdx.y * BM;
    const int n0   = blockIdx.x * BN;

    float acc[2][8][4];
#pragma unroll
    for (int mt = 0; mt < 2; mt++)
#pragma unroll
        for (int nt = 0; nt < 8; nt++)
#pragma unroll
            for (int i = 0; i < 4; i++) acc[mt][nt][i] = 0.f;

    for (int kt = 0; kt < K; kt += BK) {
#pragma unroll
        for (int i = 0; i < 4; i++) {
            int pos = tid + i * 256;
            int r   = pos >> 3;
            int cv  = (pos & 7) * 4;
            float4 v = make_float4(0.f, 0.f, 0.f, 0.f);
            if (m0 + r < M)
                v = *(const float4*)(A + (size_t)(m0 + r) * K + kt + cv);
            As[r][cv + 0] = f2tf32(v.x);
            As[r][cv + 1] = f2tf32(v.y);
            As[r][cv + 2] = f2tf32(v.z);
            As[r][cv + 3] = f2tf32(v.w);
        }
#pragma unroll
        for (int i = 0; i < 4; i++) {
            int pos = tid + i * 256;
            int r   = pos >> 5;
            int cv  = (pos & 31) * 4;
            float4 v = *(const float4*)(B + (size_t)(kt + r) * N + n0 + cv);
            Bs[r][cv + 0] = f2tf32(v.x);
            Bs[r][cv + 1] = f2tf32(v.y);
            Bs[r][cv + 2] = f2tf32(v.z);
            Bs[r][cv + 3] = f2tf32(v.w);
        }
        __syncthreads();

#pragma unroll
        for (int ks = 0; ks < 4; ks++) {
            const int kb = ks * 8;
            uint32_t a[2][4];
#pragma unroll
            for (int mt = 0; mt < 2; mt++) {
                const int row = wm * 32 + mt * 16;
                a[mt][0] = __float_as_uint(As[row + g    ][kb + tig    ]);
                a[mt][1] = __float_as_uint(As[row + g + 8][kb + tig    ]);
                a[mt][2] = __float_as_uint(As[row + g    ][kb + tig + 4]);
                a[mt][3] = __float_as_uint(As[row + g + 8][kb + tig + 4]);
            }
            uint32_t b[8][2];
#pragma unroll
            for (int nt = 0; nt < 8; nt++) {
                const int col = wn * 64 + nt * 8 + g;
                b[nt][0] = __float_as_uint(Bs[kb + tig    ][col]);
                b[nt][1] = __float_as_uint(Bs[kb + tig + 4][col]);
            }
#pragma unroll
            for (int mt = 0; mt < 2; mt++)
#pragma unroll
                for (int nt = 0; nt < 8; nt++)
                    mma_tf32(acc[mt][nt], a[mt], b[nt]);
        }
        __syncthreads();
    }

#pragma unroll
    for (int mt = 0; mt < 2; mt++) {
        const int row0 = m0 + wm * 32 + mt * 16 + g;
#pragma unroll
        for (int nt = 0; nt < 8; nt++) {
            const int col = n0 + wn * 64 + nt * 8 + tig * 2;
            const float2 bv = *(const float2*)(bias + col);
            if (row0 < M) {
                float2 r0 = make_float2(acc[mt][nt][0] + bv.x, acc[mt][nt][1] + bv.y);
                *(float2*)(C + (size_t)row0 * N + col) = r0;
            }
            if (row0 + 8 < M) {
                float2 r1 = make_float2(acc[mt][nt][2] + bv.x, acc[mt][nt][3] + bv.y);
                *(float2*)(C + (size_t)(row0 + 8) * N + col) = r1;
            }
        }
    }
}

// ---------------------------------------------------------------------------
// Tensor-core attention: one CTA per (window b, head h). 256 threads, 8 warps.
// QK^T and AV on mma.sync tf32 with 3-term split (~fp32 accuracy).
// SMEM strides chosen conflict-free for all mma fragment loads:
//   Ks/Qb stride 68 -> bank 4g+tig ; Vs stride 72 -> 8*tig+g ; at stride 204 -> 12g+tig
// ---------------------------------------------------------------------------
#define QK_STR 68
#define V_STR  72
#define AT_STR 204
#define KS_ROWS 200   // 196 + zero pad

#define ATTN_SMEM_FLOATS (KS_ROWS*QK_STR + KS_ROWS*V_STR + 64*QK_STR + 64*AT_STR + 64*14 + 64*14)
#define ATTN_SMEM_BYTES  (ATTN_SMEM_FLOATS * 4)

__global__ __launch_bounds__(256, 1)
void attn_mma_kernel(const float* __restrict__ qkv,
                     const float* __restrict__ rph,
                     const float* __restrict__ rpw,
                     float* __restrict__ ctx) {
    extern __shared__ float sm[];
    float* Ks  = sm;                          // [200][68] K row-major, rows 196..199 zero
    float* Vs  = Ks  + KS_ROWS * QK_STR;      // [200][72] V row-major, rows 196..199 zero
    float* Qb  = Vs  + KS_ROWS * V_STR;       // [64][68]  current q-block
    float* at  = Qb  + 64 * QK_STR;           // [64][204] logits/probs (cols 0..199 used)
    float* rlh = at  + 64 * AT_STR;           // [64][14]
    float* rlw = rlh + 64 * 14;               // [64][14]

    const int bh   = blockIdx.x;
    const int b    = bh / NH;
    const int h    = bh % NH;
    const int tid  = threadIdx.x;
    const int warp = tid >> 5;
    const int lane = tid & 31;
    const int g    = lane >> 2;     // 0..7
    const int tig  = lane & 3;      // 0..3
    const int wm   = warp >> 1;     // m-tile 0..3 (16 rows each)
    const int wh   = warp & 1;      // n-half
    const float scale = 0.125f;

    const float* qkv_b = qkv + (size_t)b * HW * QKV_N;

    // Stage K and V row-major (float4), then zero pad rows 196..199
    for (int slot = tid; slot < HW * 16; slot += 256) {
        int s  = slot >> 4;
        int d4 = (slot & 15) << 2;
        const float* base = qkv_b + (size_t)s * QKV_N + h * HD + d4;
        *(float4*)&Ks[s * QK_STR + d4] = *(const float4*)(base + C_DIM);
        *(float4*)&Vs[s * V_STR  + d4] = *(const float4*)(base + 2 * C_DIM);
    }
    {
        float4 z = make_float4(0.f, 0.f, 0.f, 0.f);
        for (int slot = tid; slot < 4 * 16; slot += 256) {
            int r  = 196 + (slot >> 4);
            int d4 = (slot & 15) << 2;
            *(float4*)&Ks[r * QK_STR + d4] = z;
            *(float4*)&Vs[r * V_STR  + d4] = z;
        }
    }

    for (int qb = 0; qb < 4; qb++) {
        const int qbase = qb * 64;
        __syncthreads();

        // Stage Q block (zeros past row 195)
        for (int slot = tid; slot < 64 * 16; slot += 256) {
            int ql = slot >> 4;
            int d4 = (slot & 15) << 2;
            int s  = qbase + ql;
            float4 v = make_float4(0.f, 0.f, 0.f, 0.f);
            if (s < HW)
                v = *(const float4*)(qkv_b + (size_t)s * QKV_N + h * HD + d4);
            *(float4*)&Qb[ql * QK_STR + d4] = v;
        }
        __syncthreads();

        // Rel-pos tables (fp32): rlh[q][kh] = q . rel_pos_h[hq-kh+13], same for w
        for (int idx = tid; idx < 64 * S_DIM; idx += 256) {
            int ql = idx / S_DIM;
            int kk = idx % S_DIM;
            int s  = qbase + ql;
            float sh = 0.f, sw = 0.f;
            if (s < HW) {
                int hq = s / S_DIM;
                int wq = s % S_DIM;
                const float* ph = rph + (hq - kk + S_DIM - 1) * HD;
                const float* pw = rpw + (wq - kk + S_DIM - 1) * HD;
#pragma unroll 8
                for (int d = 0; d < HD; d++) {
                    float qv = Qb[ql * QK_STR + d];
                    sh += qv * ph[d];
                    sw += qv * pw[d];
                }
            }
            rlh[ql * S_DIM + kk] = sh;
            rlw[ql * S_DIM + kk] = sw;
        }
        __syncthreads();

        // ---- QK^T via tf32 mma (3-term split): at[64][200] ----
        {
            const int rB = wm * 16;
            // Hoist A fragments (all 8 k-chunks), hi+lo
            uint32_t ah[8][4], al[8][4];
#pragma unroll
            for (int kc = 0; kc < 8; kc++) {
                const int kb = kc * 8;
                split_tf32(Qb[(rB + g    ) * QK_STR + kb + tig    ], ah[kc][0], al[kc][0]);
                split_tf32(Qb[(rB + g + 8) * QK_STR + kb + tig    ], ah[kc][1], al[kc][1]);
                split_tf32(Qb[(rB + g    ) * QK_STR + kb + tig + 4], ah[kc][2], al[kc][2]);
                split_tf32(Qb[(rB + g + 8) * QK_STR + kb + tig + 4], ah[kc][3], al[kc][3]);
            }
            const int ntb = wh * 13;
            const int nte = wh ? 25 : 13;
            for (int nt = ntb; nt < nte; nt++) {
                float acc[4] = {0.f, 0.f, 0.f, 0.f};
                const int col = nt * 8 + g;
#pragma unroll
                for (int kc = 0; kc < 8; kc++) {
                    const int kb = kc * 8;
                    uint32_t bhh[2], bll[2];
                    split_tf32(Ks[col * QK_STR + kb + tig    ], bhh[0], bll[0]);
                    split_tf32(Ks[col * QK_STR + kb + tig + 4], bhh[1], bll[1]);
                    mma_tf32(acc, ah[kc], bhh);
                    mma_tf32(acc, al[kc], bhh);
                    mma_tf32(acc, ah[kc], bll);
                }
                // Epilogue: scale + rel-pos bias; pad cols get -inf
                const int r0 = rB + g;
                const int r1 = r0 + 8;
                const int c0 = nt * 8 + 2 * tig;
                const int c1 = c0 + 1;
                if (c0 < HW) {
                    at[r0 * AT_STR + c0] = acc[0] * scale + rlh[r0 * S_DIM + c0 / S_DIM] + rlw[r0 * S_DIM + c0 % S_DIM];
                    at[r1 * AT_STR + c0] = acc[2] * scale + rlh[r1 * S_DIM + c0 / S_DIM] + rlw[r1 * S_DIM + c0 % S_DIM];
                } else {
                    at[r0 * AT_STR + c0] = -1e30f;
                    at[r1 * AT_STR + c0] = -1e30f;
                }
                if (c1 < HW) {
                    at[r0 * AT_STR + c1] = acc[1] * scale + rlh[r0 * S_DIM + c1 / S_DIM] + rlw[r0 * S_DIM + c1 % S_DIM];
                    at[r1 * AT_STR + c1] = acc[3] * scale + rlh[r1 * S_DIM + c1 / S_DIM] + rlw[r1 * S_DIM + c1 % S_DIM];
                } else {
                    at[r0 * AT_STR + c1] = -1e30f;
                    at[r1 * AT_STR + c1] = -1e30f;
                }
            }
        }
        __syncthreads();

        // ---- softmax per row (8 warps x 8 rows), cols 0..199 ----
        for (int r = warp; r < 64; r += 8) {
            float mx = -1e30f;
            for (int k = lane; k < 200; k += 32) mx = fmaxf(mx, at[r * AT_STR + k]);
#pragma unroll
            for (int o = 16; o > 0; o >>= 1) mx = fmaxf(mx, __shfl_xor_sync(0xffffffffu, mx, o));
            float sum = 0.f;
            for (int k = lane; k < 200; k += 32) {
                float e = __expf(at[r * AT_STR + k] - mx);
                at[r * AT_STR + k] = e;
                sum += e;
            }
#pragma unroll
            for (int o = 16; o > 0; o >>= 1) sum += __shfl_xor_sync(0xffffffffu, sum, o);
            float inv = 1.0f / sum;
            for (int k = lane; k < 200; k += 32) at[r * AT_STR + k] *= inv;
        }
        __syncthreads();

        // ---- AV via tf32 mma (3-term split): out[64][64] ----
        {
            const int rB = wm * 16;
            float acc2[4][4];
#pragma unroll
            for (int nt = 0; nt < 4; nt++)
#pragma unroll
                for (int i = 0; i < 4; i++) acc2[nt][i] = 0.f;

            for (int kc = 0; kc < 25; kc++) {
                const int kb = kc * 8;
                uint32_t ahh[4], all[4];
                split_tf32(at[(rB + g    ) * AT_STR + kb + tig    ], ahh[0], all[0]);
                split_tf32(at[(rB + g + 8) * AT_STR + kb + tig    ], ahh[1], all[1]);
                split_tf32(at[(rB + g    ) * AT_STR + kb + tig + 4], ahh[2], all[2]);
                split_tf32(at[(rB + g + 8) * AT_STR + kb + tig + 4], ahh[3], all[3]);
#pragma unroll
                for (int nt = 0; nt < 4; nt++) {
                    const int col = wh * 32 + nt * 8 + g;
                    uint32_t bhh[2], bll[2];
                    split_tf32(Vs[(kb + tig    ) * V_STR + col], bhh[0], bll[0]);
                    split_tf32(Vs[(kb + tig + 4) * V_STR + col], bhh[1], bll[1]);
                    mma_tf32(acc2[nt], ahh, bhh);
                    mma_tf32(acc2[nt], all, bhh);
                    mma_tf32(acc2[nt], ahh, bll);
                }
            }
            // Write context (head-merged layout)
            const int s0 = qbase + rB + g;
            const int s1 = s0 + 8;
#pragma unroll
            for (int nt = 0; nt < 4; nt++) {
                const int d = wh * 32 + nt * 8 + 2 * tig;
                if (s0 < HW) {
                    float2 r0 = make_float2(acc2[nt][0], acc2[nt][1]);
                    *(float2*)(ctx + (size_t)(b * HW + s0) * C_DIM + h * HD + d) = r0;
                }
                if (s1 < HW) {
                    float2 r1 = make_float2(acc2[nt][2], acc2[nt][3]);
                    *(float2*)(ctx + (size_t)(b * HW + s1) * C_DIM + h * HD + d) = r1;
                }
            }
        }
    }
}

// ---------------------------------------------------------------------------
extern "C" void kernel_launch(void* const* d_in, const int* in_sizes, int n_in,
                              void* d_out, int out_size) {
    const float* x      = (const float*)d_in[0];
    const float* w_qkv  = (const float*)d_in[1];
    const float* b_qkv  = (const float*)d_in[2];
    const float* w_proj = (const float*)d_in[3];
    const float* b_proj = (const float*)d_in[4];
    const float* rph    = (const float*)d_in[5];
    const float* rpw    = (const float*)d_in[6];
    float* out = (float*)d_out;

    float *qkv_ptr = nullptr, *ctx_ptr = nullptr;
    cudaGetSymbolAddress((void**)&qkv_ptr, g_qkv);
    cudaGetSymbolAddress((void**)&ctx_ptr, g_ctx);

    static bool attr_set = false;
    if (!attr_set) {
        cudaFuncSetAttribute(attn_mma_kernel,
                             cudaFuncAttributeMaxDynamicSharedMemorySize,
                             ATTN_SMEM_BYTES);
        attr_set = true;
    }

    // 1) QKV projection (tf32 tensor core)
    {
        dim3 grid(QKV_N / BN, (M_TOK + BM - 1) / BM);
        gemm_tf32_bias<<<grid, 256>>>(x, w_qkv, b_qkv, qkv_ptr,
                                      M_TOK, QKV_N, C_DIM);
    }

    // 2) Fused attention per (window, head) — tensor-core tf32x3
    attn_mma_kernel<<<B_WIN * NH, 256, ATTN_SMEM_BYTES>>>(qkv_ptr, rph, rpw, ctx_ptr);

    // 3) Output projection (tf32 tensor core)
    {
        dim3 grid(C_DIM / BN, (M_TOK + BM - 1) / BM);
        gemm_tf32_bias<<<grid, 256>>>(ctx_ptr, w_proj, b_proj, out,
                                      M_TOK, C_DIM, C_DIM);
    }
}

// round 4
// speedup vs baseline: 2.2010x; 1.2916x over previous
#include <cuda_runtime.h>
#include <cstdint>
#include <cstddef>

// Problem constants
#define B_WIN  200
#define S_DIM  14
#define HW     196           // 14*14
#define C_DIM  768
#define NH     12
#define HD     64
#define M_TOK  (B_WIN * HW)  // 39200
#define QKV_N  (3 * C_DIM)   // 2304

// Scratch (device globals: allocation-free per harness rules)
__device__ float g_qkv[(size_t)M_TOK * QKV_N];   // (B*HW, 2304)
__device__ float g_ctx[(size_t)M_TOK * C_DIM];   // (B*HW, 768) head-merged context

// ---------------------------------------------------------------------------
// tf32 helpers
// ---------------------------------------------------------------------------
__device__ __forceinline__ float f2tf32(float x) {
    uint32_t r;
    asm("cvt.rna.tf32.f32 %0, %1;" : "=r"(r) : "f"(x));
    return __uint_as_float(r);
}

__device__ __forceinline__ void mma_tf32(float* c, const uint32_t* a, const uint32_t* b) {
    asm volatile(
        "mma.sync.aligned.m16n8k8.row.col.f32.tf32.tf32.f32 "
        "{%0,%1,%2,%3}, {%4,%5,%6,%7}, {%8,%9}, {%0,%1,%2,%3};"
        : "+f"(c[0]), "+f"(c[1]), "+f"(c[2]), "+f"(c[3])
        : "r"(a[0]), "r"(a[1]), "r"(a[2]), "r"(a[3]),
          "r"(b[0]), "r"(b[1]));
}

// ---------------------------------------------------------------------------
// Tensor-core tf32 GEMM: C = A(MxK) @ B(KxN) + bias(N), row-major fp32.
// (unchanged from R2/R3)
// ---------------------------------------------------------------------------
#define BM 128
#define BN 128
#define BK 32

__global__ __launch_bounds__(256, 2)
void gemm_tf32_bias(const float* __restrict__ A, const float* __restrict__ B,
                    const float* __restrict__ bias, float* __restrict__ C,
                    int M, int N, int K) {
    __shared__ float As[BM][BK + 4];
    __shared__ float Bs[BK][BN + 8];

    const int tid  = threadIdx.x;
    const int warp = tid >> 5;
    const int lane = tid & 31;
    const int wm   = warp >> 1;
    const int wn   = warp & 1;
    const int g    = lane >> 2;
    const int tig  = lane & 3;
    const int m0   = blockIdx.y * BM;
    const int n0   = blockIdx.x * BN;

    float acc[2][8][4];
#pragma unroll
    for (int mt = 0; mt < 2; mt++)
#pragma unroll
        for (int nt = 0; nt < 8; nt++)
#pragma unroll
            for (int i = 0; i < 4; i++) acc[mt][nt][i] = 0.f;

    for (int kt = 0; kt < K; kt += BK) {
#pragma unroll
        for (int i = 0; i < 4; i++) {
            int pos = tid + i * 256;
            int r   = pos >> 3;
            int cv  = (pos & 7) * 4;
            float4 v = make_float4(0.f, 0.f, 0.f, 0.f);
            if (m0 + r < M)
                v = *(const float4*)(A + (size_t)(m0 + r) * K + kt + cv);
            As[r][cv + 0] = f2tf32(v.x);
            As[r][cv + 1] = f2tf32(v.y);
            As[r][cv + 2] = f2tf32(v.z);
            As[r][cv + 3] = f2tf32(v.w);
        }
#pragma unroll
        for (int i = 0; i < 4; i++) {
            int pos = tid + i * 256;
            int r   = pos >> 5;
            int cv  = (pos & 31) * 4;
            float4 v = *(const float4*)(B + (size_t)(kt + r) * N + n0 + cv);
            Bs[r][cv + 0] = f2tf32(v.x);
            Bs[r][cv + 1] = f2tf32(v.y);
            Bs[r][cv + 2] = f2tf32(v.z);
            Bs[r][cv + 3] = f2tf32(v.w);
        }
        __syncthreads();

#pragma unroll
        for (int ks = 0; ks < 4; ks++) {
            const int kb = ks * 8;
            uint32_t a[2][4];
#pragma unroll
            for (int mt = 0; mt < 2; mt++) {
                const int row = wm * 32 + mt * 16;
                a[mt][0] = __float_as_uint(As[row + g    ][kb + tig    ]);
                a[mt][1] = __float_as_uint(As[row + g + 8][kb + tig    ]);
                a[mt][2] = __float_as_uint(As[row + g    ][kb + tig + 4]);
                a[mt][3] = __float_as_uint(As[row + g + 8][kb + tig + 4]);
            }
            uint32_t b[8][2];
#pragma unroll
            for (int nt = 0; nt < 8; nt++) {
                const int col = wn * 64 + nt * 8 + g;
                b[nt][0] = __float_as_uint(Bs[kb + tig    ][col]);
                b[nt][1] = __float_as_uint(Bs[kb + tig + 4][col]);
            }
#pragma unroll
            for (int mt = 0; mt < 2; mt++)
#pragma unroll
                for (int nt = 0; nt < 8; nt++)
                    mma_tf32(acc[mt][nt], a[mt], b[nt]);
        }
        __syncthreads();
    }

#pragma unroll
    for (int mt = 0; mt < 2; mt++) {
        const int row0 = m0 + wm * 32 + mt * 16 + g;
#pragma unroll
        for (int nt = 0; nt < 8; nt++) {
            const int col = n0 + wn * 64 + nt * 8 + tig * 2;
            const float2 bv = *(const float2*)(bias + col);
            if (row0 < M) {
                float2 r0 = make_float2(acc[mt][nt][0] + bv.x, acc[mt][nt][1] + bv.y);
                *(float2*)(C + (size_t)row0 * N + col) = r0;
            }
            if (row0 + 8 < M) {
                float2 r1 = make_float2(acc[mt][nt][2] + bv.x, acc[mt][nt][3] + bv.y);
                *(float2*)(C + (size_t)(row0 + 8) * N + col) = r1;
            }
        }
    }
}

// ---------------------------------------------------------------------------
// Tensor-core attention v2: one CTA per (window b, head h). 512 threads,
// 16 warps in 4(m) x 4(n). Single-pass tf32 mma; operands rounded to tf32
// ONCE at staging (rna), inner loops are pure LDS + MMA.
// Conflict-free fragment banks: Ks/Qb stride 68 (4g+tig), Vs stride 72
// (8tig+g), at stride 204 (12g+tig) — all bijective over the warp.
// ---------------------------------------------------------------------------
#define QK_STR 68
#define V_STR  72
#define AT_STR 204
#define KS_ROWS 200   // 196 + zero pad

#define ATTN_SMEM_FLOATS (KS_ROWS*QK_STR + KS_ROWS*V_STR + 64*QK_STR + 64*AT_STR + 64*14 + 64*14)
#define ATTN_SMEM_BYTES  (ATTN_SMEM_FLOATS * 4)

__constant__ int c_qk_nt[5] = {0, 7, 13, 19, 25};  // nt ranges per wn

__global__ __launch_bounds__(512, 1)
void attn_mma_kernel(const float* __restrict__ qkv,
                     const float* __restrict__ rph,
                     const float* __restrict__ rpw,
                     float* __restrict__ ctx) {
    extern __shared__ float sm[];
    float* Ks  = sm;                          // [200][68] K (tf32-rounded), rows 196..199 zero
    float* Vs  = Ks  + KS_ROWS * QK_STR;      // [200][72] V (tf32-rounded)
    float* Qb  = Vs  + KS_ROWS * V_STR;       // [64][68]  q-block (tf32-rounded)
    float* at  = Qb  + 64 * QK_STR;           // [64][204] logits -> probs (tf32-rounded)
    float* rlh = at  + 64 * AT_STR;           // [64][14]
    float* rlw = rlh + 64 * 14;               // [64][14]

    const int bh   = blockIdx.x;
    const int b    = bh / NH;
    const int h    = bh % NH;
    const int tid  = threadIdx.x;
    const int warp = tid >> 5;
    const int lane = tid & 31;
    const int g    = lane >> 2;     // 0..7
    const int tig  = lane & 3;      // 0..3
    const int wm   = warp >> 2;     // 0..3 : 16-row m-tile
    const int wn   = warp & 3;      // 0..3 : n-slice
    const float scale = 0.125f;

    const float* qkv_b = qkv + (size_t)b * HW * QKV_N;

    // Stage K and V (tf32-rounded), zero pad rows 196..199
    for (int slot = tid; slot < HW * 16; slot += 512) {
        int s  = slot >> 4;
        int d4 = (slot & 15) << 2;
        const float* base = qkv_b + (size_t)s * QKV_N + h * HD + d4;
        float4 kv = *(const float4*)(base + C_DIM);
        float4 vv = *(const float4*)(base + 2 * C_DIM);
        kv.x = f2tf32(kv.x); kv.y = f2tf32(kv.y); kv.z = f2tf32(kv.z); kv.w = f2tf32(kv.w);
        vv.x = f2tf32(vv.x); vv.y = f2tf32(vv.y); vv.z = f2tf32(vv.z); vv.w = f2tf32(vv.w);
        *(float4*)&Ks[s * QK_STR + d4] = kv;
        *(float4*)&Vs[s * V_STR  + d4] = vv;
    }
    {
        float4 z = make_float4(0.f, 0.f, 0.f, 0.f);
        for (int slot = tid; slot < 4 * 16; slot += 512) {
            int r  = 196 + (slot >> 4);
            int d4 = (slot & 15) << 2;
            *(float4*)&Ks[r * QK_STR + d4] = z;
            *(float4*)&Vs[r * V_STR  + d4] = z;
        }
    }

    for (int qb = 0; qb < 4; qb++) {
        const int qbase = qb * 64;
        __syncthreads();

        // Stage Q block (tf32-rounded, zeros past row 195)
        for (int slot = tid; slot < 64 * 16; slot += 512) {
            int ql = slot >> 4;
            int d4 = (slot & 15) << 2;
            int s  = qbase + ql;
            float4 v = make_float4(0.f, 0.f, 0.f, 0.f);
            if (s < HW) {
                v = *(const float4*)(qkv_b + (size_t)s * QKV_N + h * HD + d4);
                v.x = f2tf32(v.x); v.y = f2tf32(v.y); v.z = f2tf32(v.z); v.w = f2tf32(v.w);
            }
            *(float4*)&Qb[ql * QK_STR + d4] = v;
        }
        __syncthreads();

        // Rel-pos tables (fp32)
        for (int idx = tid; idx < 64 * S_DIM; idx += 512) {
            int ql = idx / S_DIM;
            int kk = idx % S_DIM;
            int s  = qbase + ql;
            float sh = 0.f, sw = 0.f;
            if (s < HW) {
                int hq = s / S_DIM;
                int wq = s % S_DIM;
                const float* ph = rph + (hq - kk + S_DIM - 1) * HD;
                const float* pw = rpw + (wq - kk + S_DIM - 1) * HD;
#pragma unroll 8
                for (int d = 0; d < HD; d++) {
                    float qv = Qb[ql * QK_STR + d];
                    sh += qv * ph[d];
                    sw += qv * pw[d];
                }
            }
            rlh[ql * S_DIM + kk] = sh;
            rlw[ql * S_DIM + kk] = sw;
        }
        __syncthreads();

        // ---- QK^T via single tf32 mma: at[64][200] ----
        {
            const int rB = wm * 16;
            uint32_t a[8][4];
#pragma unroll
            for (int kc = 0; kc < 8; kc++) {
                const int kb = kc * 8;
                a[kc][0] = __float_as_uint(Qb[(rB + g    ) * QK_STR + kb + tig    ]);
                a[kc][1] = __float_as_uint(Qb[(rB + g + 8) * QK_STR + kb + tig    ]);
                a[kc][2] = __float_as_uint(Qb[(rB + g    ) * QK_STR + kb + tig + 4]);
                a[kc][3] = __float_as_uint(Qb[(rB + g + 8) * QK_STR + kb + tig + 4]);
            }
            const int ntb = c_qk_nt[wn];
            const int nte = c_qk_nt[wn + 1];
            for (int nt = ntb; nt < nte; nt++) {
                float acc[4] = {0.f, 0.f, 0.f, 0.f};
                const int col = nt * 8 + g;
#pragma unroll
                for (int kc = 0; kc < 8; kc++) {
                    const int kb = kc * 8;
                    uint32_t bf[2];
                    bf[0] = __float_as_uint(Ks[col * QK_STR + kb + tig    ]);
                    bf[1] = __float_as_uint(Ks[col * QK_STR + kb + tig + 4]);
                    mma_tf32(acc, a[kc], bf);
                }
                const int r0 = rB + g;
                const int r1 = r0 + 8;
                const int c0 = nt * 8 + 2 * tig;
                const int c1 = c0 + 1;
                if (c0 < HW) {
                    at[r0 * AT_STR + c0] = acc[0] * scale + rlh[r0 * S_DIM + c0 / S_DIM] + rlw[r0 * S_DIM + c0 % S_DIM];
                    at[r1 * AT_STR + c0] = acc[2] * scale + rlh[r1 * S_DIM + c0 / S_DIM] + rlw[r1 * S_DIM + c0 % S_DIM];
                } else {
                    at[r0 * AT_STR + c0] = -1e30f;
                    at[r1 * AT_STR + c0] = -1e30f;
                }
                if (c1 < HW) {
                    at[r0 * AT_STR + c1] = acc[1] * scale + rlh[r0 * S_DIM + c1 / S_DIM] + rlw[r0 * S_DIM + c1 % S_DIM];
                    at[r1 * AT_STR + c1] = acc[3] * scale + rlh[r1 * S_DIM + c1 / S_DIM] + rlw[r1 * S_DIM + c1 % S_DIM];
                } else {
                    at[r0 * AT_STR + c1] = -1e30f;
                    at[r1 * AT_STR + c1] = -1e30f;
                }
            }
        }
        __syncthreads();

        // ---- softmax per row (16 warps x 4 rows); probs tf32-rounded ----
        for (int r = warp; r < 64; r += 16) {
            float mx = -1e30f;
            for (int k = lane; k < 200; k += 32) mx = fmaxf(mx, at[r * AT_STR + k]);
#pragma unroll
            for (int o = 16; o > 0; o >>= 1) mx = fmaxf(mx, __shfl_xor_sync(0xffffffffu, mx, o));
            float sum = 0.f;
            float ev[7];
#pragma unroll
            for (int i = 0; i < 7; i++) {
                int k = lane + i * 32;
                float e = (k < 200) ? __expf(at[r * AT_STR + k] - mx) : 0.f;
                ev[i] = e;
                sum += e;
            }
#pragma unroll
            for (int o = 16; o > 0; o >>= 1) sum += __shfl_xor_sync(0xffffffffu, sum, o);
            float inv = 1.0f / sum;
#pragma unroll
            for (int i = 0; i < 7; i++) {
                int k = lane + i * 32;
                if (k < 200) at[r * AT_STR + k] = f2tf32(ev[i] * inv);
            }
        }
        __syncthreads();

        // ---- AV via single tf32 mma: out[64][64] ----
        {
            const int rB = wm * 16;
            float acc2[2][4];
#pragma unroll
            for (int nt = 0; nt < 2; nt++)
#pragma unroll
                for (int i = 0; i < 4; i++) acc2[nt][i] = 0.f;

            for (int kc = 0; kc < 25; kc++) {
                const int kb = kc * 8;
                uint32_t a[4];
                a[0] = __float_as_uint(at[(rB + g    ) * AT_STR + kb + tig    ]);
                a[1] = __float_as_uint(at[(rB + g + 8) * AT_STR + kb + tig    ]);
                a[2] = __float_as_uint(at[(rB + g    ) * AT_STR + kb + tig + 4]);
                a[3] = __float_as_uint(at[(rB + g + 8) * AT_STR + kb + tig + 4]);
#pragma unroll
                for (int nt = 0; nt < 2; nt++) {
                    const int col = wn * 16 + nt * 8 + g;
                    uint32_t bf[2];
                    bf[0] = __float_as_uint(Vs[(kb + tig    ) * V_STR + col]);
                    bf[1] = __float_as_uint(Vs[(kb + tig + 4) * V_STR + col]);
                    mma_tf32(acc2[nt], a, bf);
                }
            }
            const int s0 = qbase + rB + g;
            const int s1 = s0 + 8;
#pragma unroll
            for (int nt = 0; nt < 2; nt++) {
                const int d = wn * 16 + nt * 8 + 2 * tig;
                if (s0 < HW) {
                    float2 r0 = make_float2(acc2[nt][0], acc2[nt][1]);
                    *(float2*)(ctx + (size_t)(b * HW + s0) * C_DIM + h * HD + d) = r0;
                }
                if (s1 < HW) {
                    float2 r1 = make_float2(acc2[nt][2], acc2[nt][3]);
                    *(float2*)(ctx + (size_t)(b * HW + s1) * C_DIM + h * HD + d) = r1;
                }
            }
        }
    }
}

// ---------------------------------------------------------------------------
extern "C" void kernel_launch(void* const* d_in, const int* in_sizes, int n_in,
                              void* d_out, int out_size) {
    const float* x      = (const float*)d_in[0];
    const float* w_qkv  = (const float*)d_in[1];
    const float* b_qkv  = (const float*)d_in[2];
    const float* w_proj = (const float*)d_in[3];
    const float* b_proj = (const float*)d_in[4];
    const float* rph    = (const float*)d_in[5];
    const float* rpw    = (const float*)d_in[6];
    float* out = (float*)d_out;

    float *qkv_ptr = nullptr, *ctx_ptr = nullptr;
    cudaGetSymbolAddress((void**)&qkv_ptr, g_qkv);
    cudaGetSymbolAddress((void**)&ctx_ptr, g_ctx);

    static bool attr_set = false;
    if (!attr_set) {
        cudaFuncSetAttribute(attn_mma_kernel,
                             cudaFuncAttributeMaxDynamicSharedMemorySize,
                             ATTN_SMEM_BYTES);
        attr_set = true;
    }

    // 1) QKV projection (tf32 tensor core)
    {
        dim3 grid(QKV_N / BN, (M_TOK + BM - 1) / BM);
        gemm_tf32_bias<<<grid, 256>>>(x, w_qkv, b_qkv, qkv_ptr,
                                      M_TOK, QKV_N, C_DIM);
    }

    // 2) Fused attention per (window, head) — single-pass tf32 mma
    attn_mma_kernel<<<B_WIN * NH, 512, ATTN_SMEM_BYTES>>>(qkv_ptr, rph, rpw, ctx_ptr);

    // 3) Output projection (tf32 tensor core)
    {
        dim3 grid(C_DIM / BN, (M_TOK + BM - 1) / BM);
        gemm_tf32_bias<<<grid, 256>>>(ctx_ptr, w_proj, b_proj, out,
                                      M_TOK, C_DIM, C_DIM);
    }
}

// round 5
// speedup vs baseline: 3.5182x; 1.5985x over previous
#include <cuda_runtime.h>
#include <cstdint>
#include <cstddef>

// Problem constants
#define B_WIN  200
#define S_DIM  14
#define HW     196           // 14*14
#define C_DIM  768
#define NH     12
#define HD     64
#define M_TOK  (B_WIN * HW)  // 39200
#define QKV_N  (3 * C_DIM)   // 2304
#define NHEADS_TOT (B_WIN * NH)   // 2400

// Scratch (device globals: allocation-free per harness rules)
__device__ float g_qkv[(size_t)M_TOK * QKV_N];          // (B*HW, 2304)
__device__ float g_ctx[(size_t)M_TOK * C_DIM];          // (B*HW, 768)
__device__ float g_at[(size_t)NHEADS_TOT * HW * 200];   // probs (tf32), row stride 200

// ---------------------------------------------------------------------------
// tf32 helpers
// ---------------------------------------------------------------------------
__device__ __forceinline__ float f2tf32(float x) {
    uint32_t r;
    asm("cvt.rna.tf32.f32 %0, %1;" : "=r"(r) : "f"(x));
    return __uint_as_float(r);
}

__device__ __forceinline__ void mma_tf32(float* c, const uint32_t* a, const uint32_t* b) {
    asm volatile(
        "mma.sync.aligned.m16n8k8.row.col.f32.tf32.tf32.f32 "
        "{%0,%1,%2,%3}, {%4,%5,%6,%7}, {%8,%9}, {%0,%1,%2,%3};"
        : "+f"(c[0]), "+f"(c[1]), "+f"(c[2]), "+f"(c[3])
        : "r"(a[0]), "r"(a[1]), "r"(a[2]), "r"(a[3]),
          "r"(b[0]), "r"(b[1]));
}

// ---------------------------------------------------------------------------
// Tensor-core tf32 GEMM: C = A(MxK) @ B(KxN) + bias(N), row-major fp32.
// (unchanged)
// ---------------------------------------------------------------------------
#define BM 128
#define BN 128
#define BK 32

__global__ __launch_bounds__(256, 2)
void gemm_tf32_bias(const float* __restrict__ A, const float* __restrict__ B,
                    const float* __restrict__ bias, float* __restrict__ C,
                    int M, int N, int K) {
    __shared__ float As[BM][BK + 4];
    __shared__ float Bs[BK][BN + 8];

    const int tid  = threadIdx.x;
    const int warp = tid >> 5;
    const int lane = tid & 31;
    const int wm   = warp >> 1;
    const int wn   = warp & 1;
    const int g    = lane >> 2;
    const int tig  = lane & 3;
    const int m0   = blockIdx.y * BM;
    const int n0   = blockIdx.x * BN;

    float acc[2][8][4];
#pragma unroll
    for (int mt = 0; mt < 2; mt++)
#pragma unroll
        for (int nt = 0; nt < 8; nt++)
#pragma unroll
            for (int i = 0; i < 4; i++) acc[mt][nt][i] = 0.f;

    for (int kt = 0; kt < K; kt += BK) {
#pragma unroll
        for (int i = 0; i < 4; i++) {
            int pos = tid + i * 256;
            int r   = pos >> 3;
            int cv  = (pos & 7) * 4;
            float4 v = make_float4(0.f, 0.f, 0.f, 0.f);
            if (m0 + r < M)
                v = *(const float4*)(A + (size_t)(m0 + r) * K + kt + cv);
            As[r][cv + 0] = f2tf32(v.x);
            As[r][cv + 1] = f2tf32(v.y);
            As[r][cv + 2] = f2tf32(v.z);
            As[r][cv + 3] = f2tf32(v.w);
        }
#pragma unroll
        for (int i = 0; i < 4; i++) {
            int pos = tid + i * 256;
            int r   = pos >> 5;
            int cv  = (pos & 31) * 4;
            float4 v = *(const float4*)(B + (size_t)(kt + r) * N + n0 + cv);
            Bs[r][cv + 0] = f2tf32(v.x);
            Bs[r][cv + 1] = f2tf32(v.y);
            Bs[r][cv + 2] = f2tf32(v.z);
            Bs[r][cv + 3] = f2tf32(v.w);
        }
        __syncthreads();

#pragma unroll
        for (int ks = 0; ks < 4; ks++) {
            const int kb = ks * 8;
            uint32_t a[2][4];
#pragma unroll
            for (int mt = 0; mt < 2; mt++) {
                const int row = wm * 32 + mt * 16;
                a[mt][0] = __float_as_uint(As[row + g    ][kb + tig    ]);
                a[mt][1] = __float_as_uint(As[row + g + 8][kb + tig    ]);
                a[mt][2] = __float_as_uint(As[row + g    ][kb + tig + 4]);
                a[mt][3] = __float_as_uint(As[row + g + 8][kb + tig + 4]);
            }
            uint32_t b[8][2];
#pragma unroll
            for (int nt = 0; nt < 8; nt++) {
                const int col = wn * 64 + nt * 8 + g;
                b[nt][0] = __float_as_uint(Bs[kb + tig    ][col]);
                b[nt][1] = __float_as_uint(Bs[kb + tig + 4][col]);
            }
#pragma unroll
            for (int mt = 0; mt < 2; mt++)
#pragma unroll
                for (int nt = 0; nt < 8; nt++)
                    mma_tf32(acc[mt][nt], a[mt], b[nt]);
        }
        __syncthreads();
    }

#pragma unroll
    for (int mt = 0; mt < 2; mt++) {
        const int row0 = m0 + wm * 32 + mt * 16 + g;
#pragma unroll
        for (int nt = 0; nt < 8; nt++) {
            const int col = n0 + wn * 64 + nt * 8 + tig * 2;
            const float2 bv = *(const float2*)(bias + col);
            if (row0 < M) {
                float2 r0 = make_float2(acc[mt][nt][0] + bv.x, acc[mt][nt][1] + bv.y);
                *(float2*)(C + (size_t)row0 * N + col) = r0;
            }
            if (row0 + 8 < M) {
                float2 r1 = make_float2(acc[mt][nt][2] + bv.x, acc[mt][nt][3] + bv.y);
                *(float2*)(C + (size_t)(row0 + 8) * N + col) = r1;
            }
        }
    }
}

// ---------------------------------------------------------------------------
// Kernel L: logits + bias + softmax -> probs in g_at.
// grid = 2400*4 (bh, qblock); 256 threads (8 warps = 4m x 2n).
// Rel-pos via mma: Th = Q @ rph^T, Tw = Q @ rpw^T (64x32x64 each).
// Logits stay in registers; softmax via shfl + small SMEM cross-warp reduce.
// SMEM ~107.6KB -> 2 CTAs/SM.
// ---------------------------------------------------------------------------
#define KS_STR 68
#define T_STR  36

// float offsets in dynamic smem
#define L_KS    0
#define L_QT    (L_KS  + 200 * KS_STR)       // 13600
#define L_RPHT  (L_QT  + 64 * KS_STR)        // +4352
#define L_RPWT  (L_RPHT + 64 * T_STR)
#define L_TH    (L_RPWT + 64 * T_STR)
#define L_TW    (L_TH  + 64 * T_STR)
#define L_REDA  (L_TW  + 64 * T_STR)         // [2][64]
#define L_REDB  (L_REDA + 128)               // [2][64]
#define L_QHW   (L_REDB + 128)               // 128 ints (qh[64], qw[64])
#define L_SMEM_FLOATS (L_QHW + 128)
#define L_SMEM_BYTES  (L_SMEM_FLOATS * 4)

__global__ __launch_bounds__(256, 2)
void attn_logits_kernel(const float* __restrict__ qkv,
                        const float* __restrict__ rph,
                        const float* __restrict__ rpw,
                        float* __restrict__ at_g) {
    extern __shared__ float sm[];
    float* Ks   = sm + L_KS;      // [200][68] tf32 K, rows 196..199 zero
    float* Qt   = sm + L_QT;      // [64][68]  tf32 Q rows (zeros past 195)
    float* rphT = sm + L_RPHT;    // [64][36]  rph transposed, cols 27..35 zero
    float* rpwT = sm + L_RPWT;
    float* Th   = sm + L_TH;      // [64][36]
    float* Tw   = sm + L_TW;
    float* redA = sm + L_REDA;    // [2][64]
    float* redB = sm + L_REDB;
    int*   qhw  = (int*)(sm + L_QHW);   // qh[64], qw[64]

    const int blk  = blockIdx.x;
    const int bh   = blk >> 2;
    const int qb   = blk & 3;
    const int b    = bh / NH;
    const int h    = bh % NH;
    const int qbase = qb * 64;
    const int tid  = threadIdx.x;
    const int warp = tid >> 5;
    const int lane = tid & 31;
    const int g    = lane >> 2;
    const int tig  = lane & 3;
    const int wm   = warp >> 1;       // 0..3
    const int wn   = warp & 1;        // 0..1
    const float scale = 0.125f;

    const float* qkv_b = qkv + (size_t)b * HW * QKV_N;

    // --- stage rel tables transposed (tf32), zero pad cols ---
    for (int idx = tid; idx < 64 * T_STR; idx += 256) {
        int d = idx / T_STR;
        int j = idx % T_STR;
        rphT[d * T_STR + j] = (j < 2 * S_DIM - 1) ? f2tf32(rph[j * HD + d]) : 0.f;
        rpwT[d * T_STR + j] = (j < 2 * S_DIM - 1) ? f2tf32(rpw[j * HD + d]) : 0.f;
    }
    // --- stage K (tf32), zero pad rows ---
    for (int slot = tid; slot < 200 * 16; slot += 256) {
        int s  = slot >> 4;
        int d4 = (slot & 15) << 2;
        float4 v = make_float4(0.f, 0.f, 0.f, 0.f);
        if (s < HW) {
            v = *(const float4*)(qkv_b + (size_t)s * QKV_N + C_DIM + h * HD + d4);
            v.x = f2tf32(v.x); v.y = f2tf32(v.y); v.z = f2tf32(v.z); v.w = f2tf32(v.w);
        }
        *(float4*)&Ks[s * KS_STR + d4] = v;
    }
    // --- stage Q block (tf32) ---
    for (int slot = tid; slot < 64 * 16; slot += 256) {
        int ql = slot >> 4;
        int d4 = (slot & 15) << 2;
        int s  = qbase + ql;
        float4 v = make_float4(0.f, 0.f, 0.f, 0.f);
        if (s < HW) {
            v = *(const float4*)(qkv_b + (size_t)s * QKV_N + h * HD + d4);
            v.x = f2tf32(v.x); v.y = f2tf32(v.y); v.z = f2tf32(v.z); v.w = f2tf32(v.w);
        }
        *(float4*)&Qt[ql * KS_STR + d4] = v;
    }
    // --- qh/qw per local row ---
    if (tid < 64) {
        int s = qbase + tid;
        qhw[tid]      = s / S_DIM;
        qhw[64 + tid] = s % S_DIM;
    }
    __syncthreads();

    // --- hoist Q fragments (shared by T-mma and QK-mma) ---
    const int rB = wm * 16;
    uint32_t af[8][4];
#pragma unroll
    for (int kc = 0; kc < 8; kc++) {
        const int kb = kc * 8;
        af[kc][0] = __float_as_uint(Qt[(rB + g    ) * KS_STR + kb + tig    ]);
        af[kc][1] = __float_as_uint(Qt[(rB + g + 8) * KS_STR + kb + tig    ]);
        af[kc][2] = __float_as_uint(Qt[(rB + g    ) * KS_STR + kb + tig + 4]);
        af[kc][3] = __float_as_uint(Qt[(rB + g + 8) * KS_STR + kb + tig + 4]);
    }

    // --- T-mma: wn=0 -> Th from rphT ; wn=1 -> Tw from rpwT ---
    {
        const float* Bt = wn ? rpwT : rphT;
        float*       Dt = wn ? Tw   : Th;
#pragma unroll
        for (int nt = 0; nt < 4; nt++) {
            float acc[4] = {0.f, 0.f, 0.f, 0.f};
            const int col = nt * 8 + g;
#pragma unroll
            for (int kc = 0; kc < 8; kc++) {
                const int kb = kc * 8;
                uint32_t bf[2];
                bf[0] = __float_as_uint(Bt[(kb + tig    ) * T_STR + col]);
                bf[1] = __float_as_uint(Bt[(kb + tig + 4) * T_STR + col]);
                mma_tf32(acc, af[kc], bf);
            }
            const int c0 = nt * 8 + 2 * tig;
            Dt[(rB + g    ) * T_STR + c0    ] = acc[0];
            Dt[(rB + g    ) * T_STR + c0 + 1] = acc[1];
            Dt[(rB + g + 8) * T_STR + c0    ] = acc[2];
            Dt[(rB + g + 8) * T_STR + c0 + 1] = acc[3];
        }
    }
    __syncthreads();

    // --- QK^T: 13 n-tiles per warp; logits in registers ---
    const int r0 = rB + g;
    const int r1 = r0 + 8;
    const int qh0 = qhw[r0],      qw0 = qhw[64 + r0];
    const int qh1 = qhw[r1],      qw1 = qhw[64 + r1];
    float lg[13][4];
#pragma unroll
    for (int it = 0; it < 13; it++) {
        const int nt  = wn * 13 + it;   // wn=1,it=12 -> nt=25 (cols >=196, discarded)
        float acc[4] = {0.f, 0.f, 0.f, 0.f};
        const int col = nt * 8 + g;
#pragma unroll
        for (int kc = 0; kc < 8; kc++) {
            const int kb = kc * 8;
            uint32_t bf[2];
            bf[0] = __float_as_uint(Ks[col * KS_STR + kb + tig    ]);
            bf[1] = __float_as_uint(Ks[col * KS_STR + kb + tig + 4]);
            mma_tf32(acc, af[kc], bf);
        }
        const int c0 = nt * 8 + 2 * tig;
        const int c1 = c0 + 1;
        if (c0 < HW) {
            int kh = c0 / S_DIM, kw = c0 % S_DIM;
            lg[it][0] = acc[0] * scale + Th[r0 * T_STR + qh0 - kh + 13] + Tw[r0 * T_STR + qw0 - kw + 13];
            lg[it][2] = acc[2] * scale + Th[r1 * T_STR + qh1 - kh + 13] + Tw[r1 * T_STR + qw1 - kw + 13];
        } else { lg[it][0] = -1e30f; lg[it][2] = -1e30f; }
        if (c1 < HW) {
            int kh = c1 / S_DIM, kw = c1 % S_DIM;
            lg[it][1] = acc[1] * scale + Th[r0 * T_STR + qh0 - kh + 13] + Tw[r0 * T_STR + qw0 - kw + 13];
            lg[it][3] = acc[3] * scale + Th[r1 * T_STR + qh1 - kh + 13] + Tw[r1 * T_STR + qw1 - kw + 13];
        } else { lg[it][1] = -1e30f; lg[it][3] = -1e30f; }
    }

    // --- softmax: max ---
    float m0 = -1e30f, m1 = -1e30f;
#pragma unroll
    for (int it = 0; it < 13; it++) {
        m0 = fmaxf(m0, fmaxf(lg[it][0], lg[it][1]));
        m1 = fmaxf(m1, fmaxf(lg[it][2], lg[it][3]));
    }
    m0 = fmaxf(m0, __shfl_xor_sync(0xffffffffu, m0, 1));
    m0 = fmaxf(m0, __shfl_xor_sync(0xffffffffu, m0, 2));
    m1 = fmaxf(m1, __shfl_xor_sync(0xffffffffu, m1, 1));
    m1 = fmaxf(m1, __shfl_xor_sync(0xffffffffu, m1, 2));
    if (tig == 0) { redA[wn * 64 + r0] = m0; redA[wn * 64 + r1] = m1; }
    __syncthreads();
    const float M0 = fmaxf(redA[r0], redA[64 + r0]);
    const float M1 = fmaxf(redA[r1], redA[64 + r1]);

    // --- softmax: exp + sum ---
    float s0 = 0.f, s1 = 0.f;
#pragma unroll
    for (int it = 0; it < 13; it++) {
        float e0 = __expf(lg[it][0] - M0); lg[it][0] = e0; s0 += e0;
        float e1 = __expf(lg[it][1] - M0); lg[it][1] = e1; s0 += e1;
        float e2 = __expf(lg[it][2] - M1); lg[it][2] = e2; s1 += e2;
        float e3 = __expf(lg[it][3] - M1); lg[it][3] = e3; s1 += e3;
    }
    s0 += __shfl_xor_sync(0xffffffffu, s0, 1);
    s0 += __shfl_xor_sync(0xffffffffu, s0, 2);
    s1 += __shfl_xor_sync(0xffffffffu, s1, 1);
    s1 += __shfl_xor_sync(0xffffffffu, s1, 2);
    if (tig == 0) { redB[wn * 64 + r0] = s0; redB[wn * 64 + r1] = s1; }
    __syncthreads();
    const float inv0 = 1.0f / (redB[r0] + redB[64 + r0]);
    const float inv1 = 1.0f / (redB[r1] + redB[64 + r1]);

    // --- write probs (tf32-rounded) ---
    const int row0 = qbase + r0;
    const int row1 = qbase + r1;
    float* atr0 = at_g + ((size_t)bh * HW + row0) * 200;
    float* atr1 = at_g + ((size_t)bh * HW + row1) * 200;
#pragma unroll
    for (int it = 0; it < 13; it++) {
        const int nt = wn * 13 + it;
        const int c0 = nt * 8 + 2 * tig;
        if (c0 < HW) {
            if (row0 < HW) {
                float2 p = make_float2(f2tf32(lg[it][0] * inv0), f2tf32(lg[it][1] * inv0));
                *(float2*)(atr0 + c0) = p;
            }
            if (row1 < HW) {
                float2 p = make_float2(f2tf32(lg[it][2] * inv1), f2tf32(lg[it][3] * inv1));
                *(float2*)(atr1 + c0) = p;
            }
        }
    }
}

// ---------------------------------------------------------------------------
// Kernel V: out = probs @ V. grid = 2400 (bh); 256 threads (8 warps = 4m x 2n).
// SMEM: Vs[200][72] + atS[64][204]  -> 107.2KB -> 2 CTAs/SM.
// ---------------------------------------------------------------------------
#define V_STR  72
#define AT_STR 204
#define V_SMEM_FLOATS (200 * V_STR + 64 * AT_STR)
#define V_SMEM_BYTES  (V_SMEM_FLOATS * 4)

__global__ __launch_bounds__(256, 2)
void attn_av_kernel(const float* __restrict__ qkv,
                    const float* __restrict__ at_g,
                    float* __restrict__ ctx) {
    extern __shared__ float sm[];
    float* Vs  = sm;                   // [200][72] tf32 V, rows 196..199 zero
    float* atS = sm + 200 * V_STR;     // [64][204] probs tile, cols 196..199 zero

    const int bh   = blockIdx.x;
    const int b    = bh / NH;
    const int h    = bh % NH;
    const int tid  = threadIdx.x;
    const int warp = tid >> 5;
    const int lane = tid & 31;
    const int g    = lane >> 2;
    const int tig  = lane & 3;
    const int wm   = warp >> 1;     // 0..3
    const int wn   = warp & 1;      // 0..1

    const float* qkv_b = qkv + (size_t)b * HW * QKV_N;
    const float* at_b  = at_g + (size_t)bh * HW * 200;

    // Stage V (tf32), zero pad rows
    for (int slot = tid; slot < 200 * 16; slot += 256) {
        int s  = slot >> 4;
        int d4 = (slot & 15) << 2;
        float4 v = make_float4(0.f, 0.f, 0.f, 0.f);
        if (s < HW) {
            v = *(const float4*)(qkv_b + (size_t)s * QKV_N + 2 * C_DIM + h * HD + d4);
            v.x = f2tf32(v.x); v.y = f2tf32(v.y); v.z = f2tf32(v.z); v.w = f2tf32(v.w);
        }
        *(float4*)&Vs[s * V_STR + d4] = v;
    }

    for (int qb = 0; qb < 4; qb++) {
        const int qbase = qb * 64;
        __syncthreads();   // prev iter done with atS (first iter: Vs also covered)

        // Stage probs tile: 64 rows x 50 float4 (cols 196..199 -> zero)
        for (int slot = tid; slot < 64 * 50; slot += 256) {
            int rr = slot / 50;
            int c4 = slot % 50;
            int s  = qbase + rr;
            float4 v = make_float4(0.f, 0.f, 0.f, 0.f);
            if (s < HW && c4 < 49)
                v = *(const float4*)(at_b + (size_t)s * 200 + c4 * 4);
            *(float4*)&atS[rr * AT_STR + c4 * 4] = v;
        }
        __syncthreads();

        // AV mma: per warp rows rB..rB+15, cols wn*32 + nt*8 (nt 0..3)
        const int rB = wm * 16;
        float acc[4][4];
#pragma unroll
        for (int nt = 0; nt < 4; nt++)
#pragma unroll
            for (int i = 0; i < 4; i++) acc[nt][i] = 0.f;

        for (int kc = 0; kc < 25; kc++) {
            const int kb = kc * 8;
            uint32_t a[4];
            a[0] = __float_as_uint(atS[(rB + g    ) * AT_STR + kb + tig    ]);
            a[1] = __float_as_uint(atS[(rB + g + 8) * AT_STR + kb + tig    ]);
            a[2] = __float_as_uint(atS[(rB + g    ) * AT_STR + kb + tig + 4]);
            a[3] = __float_as_uint(atS[(rB + g + 8) * AT_STR + kb + tig + 4]);
#pragma unroll
            for (int nt = 0; nt < 4; nt++) {
                const int col = wn * 32 + nt * 8 + g;
                uint32_t bf[2];
                bf[0] = __float_as_uint(Vs[(kb + tig    ) * V_STR + col]);
                bf[1] = __float_as_uint(Vs[(kb + tig + 4) * V_STR + col]);
                mma_tf32(acc[nt], a, bf);
            }
        }

        const int s0 = qbase + rB + g;
        const int s1 = s0 + 8;
#pragma unroll
        for (int nt = 0; nt < 4; nt++) {
            const int d = wn * 32 + nt * 8 + 2 * tig;
            if (s0 < HW) {
                float2 r0 = make_float2(acc[nt][0], acc[nt][1]);
                *(float2*)(ctx + (size_t)(b * HW + s0) * C_DIM + h * HD + d) = r0;
            }
            if (s1 < HW) {
                float2 r1 = make_float2(acc[nt][2], acc[nt][3]);
                *(float2*)(ctx + (size_t)(b * HW + s1) * C_DIM + h * HD + d) = r1;
            }
        }
    }
}

// ---------------------------------------------------------------------------
extern "C" void kernel_launch(void* const* d_in, const int* in_sizes, int n_in,
                              void* d_out, int out_size) {
    const float* x      = (const float*)d_in[0];
    const float* w_qkv  = (const float*)d_in[1];
    const float* b_qkv  = (const float*)d_in[2];
    const float* w_proj = (const float*)d_in[3];
    const float* b_proj = (const float*)d_in[4];
    const float* rph    = (const float*)d_in[5];
    const float* rpw    = (const float*)d_in[6];
    float* out = (float*)d_out;

    float *qkv_ptr = nullptr, *ctx_ptr = nullptr, *at_ptr = nullptr;
    cudaGetSymbolAddress((void**)&qkv_ptr, g_qkv);
    cudaGetSymbolAddress((void**)&ctx_ptr, g_ctx);
    cudaGetSymbolAddress((void**)&at_ptr, g_at);

    static bool attr_set = false;
    if (!attr_set) {
        cudaFuncSetAttribute(attn_logits_kernel,
                             cudaFuncAttributeMaxDynamicSharedMemorySize,
                             L_SMEM_BYTES);
        cudaFuncSetAttribute(attn_av_kernel,
                             cudaFuncAttributeMaxDynamicSharedMemorySize,
                             V_SMEM_BYTES);
        attr_set = true;
    }

    // 1) QKV projection (tf32 tensor core)
    {
        dim3 grid(QKV_N / BN, (M_TOK + BM - 1) / BM);
        gemm_tf32_bias<<<grid, 256>>>(x, w_qkv, b_qkv, qkv_ptr,
                                      M_TOK, QKV_N, C_DIM);
    }

    // 2a) Logits + bias + softmax -> probs
    attn_logits_kernel<<<NHEADS_TOT * 4, 256, L_SMEM_BYTES>>>(qkv_ptr, rph, rpw, at_ptr);

    // 2b) AV
    attn_av_kernel<<<NHEADS_TOT, 256, V_SMEM_BYTES>>>(qkv_ptr, at_ptr, ctx_ptr);

    // 3) Output projection (tf32 tensor core)
    {
        dim3 grid(C_DIM / BN, (M_TOK + BM - 1) / BM);
        gemm_tf32_bias<<<grid, 256>>>(ctx_ptr, w_proj, b_proj, out,
                                      M_TOK, C_DIM, C_DIM);
    }
}

// round 6
// speedup vs baseline: 3.6038x; 1.0243x over previous
#include <cuda_runtime.h>
#include <cstdint>
#include <cstddef>

// Problem constants
#define B_WIN  200
#define S_DIM  14
#define HW     196           // 14*14
#define C_DIM  768
#define NH     12
#define HD     64
#define M_TOK  (B_WIN * HW)  // 39200
#define QKV_N  (3 * C_DIM)   // 2304
#define NHEADS_TOT (B_WIN * NH)   // 2400

// Scratch (device globals: allocation-free per harness rules)
__device__ float g_qkv[(size_t)M_TOK * QKV_N];          // (B*HW, 2304)
__device__ float g_ctx[(size_t)M_TOK * C_DIM];          // (B*HW, 768)
__device__ float g_at[(size_t)NHEADS_TOT * HW * 200];   // probs (tf32), row stride 200

// ---------------------------------------------------------------------------
// tf32 helpers
// ---------------------------------------------------------------------------
__device__ __forceinline__ float f2tf32(float x) {
    uint32_t r;
    asm("cvt.rna.tf32.f32 %0, %1;" : "=r"(r) : "f"(x));
    return __uint_as_float(r);
}

__device__ __forceinline__ uint32_t tf32_of(float x) {
    uint32_t r;
    asm("cvt.rna.tf32.f32 %0, %1;" : "=r"(r) : "f"(x));
    return r;
}

__device__ __forceinline__ void mma_tf32(float* c, const uint32_t* a, const uint32_t* b) {
    asm volatile(
        "mma.sync.aligned.m16n8k8.row.col.f32.tf32.tf32.f32 "
        "{%0,%1,%2,%3}, {%4,%5,%6,%7}, {%8,%9}, {%0,%1,%2,%3};"
        : "+f"(c[0]), "+f"(c[1]), "+f"(c[2]), "+f"(c[3])
        : "r"(a[0]), "r"(a[1]), "r"(a[2]), "r"(a[3]),
          "r"(b[0]), "r"(b[1]));
}

// ---------------------------------------------------------------------------
// Tensor-core tf32 GEMM with cp.async double buffering.
// C = A(MxK) @ B(KxN) + bias(N), row-major fp32. BM=BN=128, BK=32.
// SMEM holds RAW fp32 (cp.async); cvt.rna.tf32 applied at fragment load.
// Numerics identical to convert-at-staging.
// ---------------------------------------------------------------------------
#define BM 128
#define BN 128
#define BK 32

#define GA_STR 36     // As row stride (floats)
#define GB_STR 136    // Bs row stride (floats)
#define GA_SZ  (BM * GA_STR)          // 4608 floats per stage
#define GB_SZ  (BK * GB_STR)          // 4352 floats per stage
#define G_SMEM_FLOATS (2 * GA_SZ + 2 * GB_SZ)
#define G_SMEM_BYTES  (G_SMEM_FLOATS * 4)   // 71680

__global__ __launch_bounds__(256, 2)
void gemm_tf32_bias(const float* __restrict__ A, const float* __restrict__ B,
                    const float* __restrict__ bias, float* __restrict__ C,
                    int M, int N, int K) {
    extern __shared__ float sg[];
    // layout: As[2][128][36] | Bs[2][32][136]
    float* AsBase = sg;
    float* BsBase = sg + 2 * GA_SZ;

    const int tid  = threadIdx.x;
    const int warp = tid >> 5;
    const int lane = tid & 31;
    const int wm   = warp >> 1;
    const int wn   = warp & 1;
    const int g    = lane >> 2;
    const int tig  = lane & 3;
    const int m0   = blockIdx.y * BM;
    const int n0   = blockIdx.x * BN;

    const uint32_t smemA = (uint32_t)__cvta_generic_to_shared(AsBase);
    const uint32_t smemB = (uint32_t)__cvta_generic_to_shared(BsBase);

    // Per-thread staging coordinates
    const int aR = tid >> 1;                 // unused path (kept simple below)
    (void)aR;

    float acc[2][8][4];
#pragma unroll
    for (int mt = 0; mt < 2; mt++)
#pragma unroll
        for (int nt = 0; nt < 8; nt++)
#pragma unroll
            for (int i = 0; i < 4; i++) acc[mt][nt][i] = 0.f;

    const int T = K / BK;

    // --- staging macro: issue 8 cp.async per thread for tile kt -> stage st ---
    auto stage = [&](int kt, int st) {
#pragma unroll
        for (int i = 0; i < 4; i++) {
            int pos = tid + i * 256;         // 0..1023
            int r   = pos >> 3;              // 0..127
            int cv  = (pos & 7) * 4;         // 0..28
            uint32_t dst = smemA + (uint32_t)((st * GA_SZ + r * GA_STR + cv) << 2);
            const float* src = A + (size_t)(m0 + r) * K + kt + cv;
            int sz = (m0 + r < M) ? 16 : 0;  // zero-fill OOB rows
            asm volatile("cp.async.cg.shared.global [%0], [%1], 16, %2;\n"
                         :: "r"(dst), "l"(src), "r"(sz));
        }
#pragma unroll
        for (int i = 0; i < 4; i++) {
            int pos = tid + i * 256;
            int r   = pos >> 5;              // 0..31
            int cv  = (pos & 31) * 4;        // 0..124
            uint32_t dst = smemB + (uint32_t)((st * GB_SZ + r * GB_STR + cv) << 2);
            const float* src = B + (size_t)(kt + r) * N + n0 + cv;
            asm volatile("cp.async.cg.shared.global [%0], [%1], 16, 16;\n"
                         :: "r"(dst), "l"(src));
        }
        asm volatile("cp.async.commit_group;\n");
    };

    stage(0, 0);

    for (int kt = 0; kt < T; kt++) {
        const int st = kt & 1;
        if (kt + 1 < T) {
            stage((kt + 1) * BK, (kt + 1) & 1);
            asm volatile("cp.async.wait_group 1;\n");
        } else {
            asm volatile("cp.async.wait_group 0;\n");
        }
        __syncthreads();

        const float* As = AsBase + st * GA_SZ;
        const float* Bs = BsBase + st * GB_SZ;

#pragma unroll
        for (int ks = 0; ks < 4; ks++) {
            const int kb = ks * 8;
            uint32_t a[2][4];
#pragma unroll
            for (int mt = 0; mt < 2; mt++) {
                const int row = wm * 32 + mt * 16;
                a[mt][0] = tf32_of(As[(row + g    ) * GA_STR + kb + tig    ]);
                a[mt][1] = tf32_of(As[(row + g + 8) * GA_STR + kb + tig    ]);
                a[mt][2] = tf32_of(As[(row + g    ) * GA_STR + kb + tig + 4]);
                a[mt][3] = tf32_of(As[(row + g + 8) * GA_STR + kb + tig + 4]);
            }
            uint32_t b[8][2];
#pragma unroll
            for (int nt = 0; nt < 8; nt++) {
                const int col = wn * 64 + nt * 8 + g;
                b[nt][0] = tf32_of(Bs[(kb + tig    ) * GB_STR + col]);
                b[nt][1] = tf32_of(Bs[(kb + tig + 4) * GB_STR + col]);
            }
#pragma unroll
            for (int mt = 0; mt < 2; mt++)
#pragma unroll
                for (int nt = 0; nt < 8; nt++)
                    mma_tf32(acc[mt][nt], a[mt], b[nt]);
        }
        __syncthreads();
    }

#pragma unroll
    for (int mt = 0; mt < 2; mt++) {
        const int row0 = m0 + wm * 32 + mt * 16 + g;
#pragma unroll
        for (int nt = 0; nt < 8; nt++) {
            const int col = n0 + wn * 64 + nt * 8 + tig * 2;
            const float2 bv = *(const float2*)(bias + col);
            if (row0 < M) {
                float2 r0 = make_float2(acc[mt][nt][0] + bv.x, acc[mt][nt][1] + bv.y);
                *(float2*)(C + (size_t)row0 * N + col) = r0;
            }
            if (row0 + 8 < M) {
                float2 r1 = make_float2(acc[mt][nt][2] + bv.x, acc[mt][nt][3] + bv.y);
                *(float2*)(C + (size_t)(row0 + 8) * N + col) = r1;
            }
        }
    }
}

// ---------------------------------------------------------------------------
// Kernel L: logits + bias + softmax -> probs in g_at. (unchanged from R5)
// ---------------------------------------------------------------------------
#define KS_STR 68
#define T_STR  36

#define L_KS    0
#define L_QT    (L_KS  + 200 * KS_STR)
#define L_RPHT  (L_QT  + 64 * KS_STR)
#define L_RPWT  (L_RPHT + 64 * T_STR)
#define L_TH    (L_RPWT + 64 * T_STR)
#define L_TW    (L_TH  + 64 * T_STR)
#define L_REDA  (L_TW  + 64 * T_STR)
#define L_REDB  (L_REDA + 128)
#define L_QHW   (L_REDB + 128)
#define L_SMEM_FLOATS (L_QHW + 128)
#define L_SMEM_BYTES  (L_SMEM_FLOATS * 4)

__global__ __launch_bounds__(256, 2)
void attn_logits_kernel(const float* __restrict__ qkv,
                        const float* __restrict__ rph,
                        const float* __restrict__ rpw,
                        float* __restrict__ at_g) {
    extern __shared__ float sm[];
    float* Ks   = sm + L_KS;
    float* Qt   = sm + L_QT;
    float* rphT = sm + L_RPHT;
    float* rpwT = sm + L_RPWT;
    float* Th   = sm + L_TH;
    float* Tw   = sm + L_TW;
    float* redA = sm + L_REDA;
    float* redB = sm + L_REDB;
    int*   qhw  = (int*)(sm + L_QHW);

    const int blk  = blockIdx.x;
    const int bh   = blk >> 2;
    const int qb   = blk & 3;
    const int b    = bh / NH;
    const int h    = bh % NH;
    const int qbase = qb * 64;
    const int tid  = threadIdx.x;
    const int warp = tid >> 5;
    const int lane = tid & 31;
    const int g    = lane >> 2;
    const int tig  = lane & 3;
    const int wm   = warp >> 1;
    const int wn   = warp & 1;
    const float scale = 0.125f;

    const float* qkv_b = qkv + (size_t)b * HW * QKV_N;

    for (int idx = tid; idx < 64 * T_STR; idx += 256) {
        int d = idx / T_STR;
        int j = idx % T_STR;
        rphT[d * T_STR + j] = (j < 2 * S_DIM - 1) ? f2tf32(rph[j * HD + d]) : 0.f;
        rpwT[d * T_STR + j] = (j < 2 * S_DIM - 1) ? f2tf32(rpw[j * HD + d]) : 0.f;
    }
    for (int slot = tid; slot < 200 * 16; slot += 256) {
        int s  = slot >> 4;
        int d4 = (slot & 15) << 2;
        float4 v = make_float4(0.f, 0.f, 0.f, 0.f);
        if (s < HW) {
            v = *(const float4*)(qkv_b + (size_t)s * QKV_N + C_DIM + h * HD + d4);
            v.x = f2tf32(v.x); v.y = f2tf32(v.y); v.z = f2tf32(v.z); v.w = f2tf32(v.w);
        }
        *(float4*)&Ks[s * KS_STR + d4] = v;
    }
    for (int slot = tid; slot < 64 * 16; slot += 256) {
        int ql = slot >> 4;
        int d4 = (slot & 15) << 2;
        int s  = qbase + ql;
        float4 v = make_float4(0.f, 0.f, 0.f, 0.f);
        if (s < HW) {
            v = *(const float4*)(qkv_b + (size_t)s * QKV_N + h * HD + d4);
            v.x = f2tf32(v.x); v.y = f2tf32(v.y); v.z = f2tf32(v.z); v.w = f2tf32(v.w);
        }
        *(float4*)&Qt[ql * KS_STR + d4] = v;
    }
    if (tid < 64) {
        int s = qbase + tid;
        qhw[tid]      = s / S_DIM;
        qhw[64 + tid] = s % S_DIM;
    }
    __syncthreads();

    const int rB = wm * 16;
    uint32_t af[8][4];
#pragma unroll
    for (int kc = 0; kc < 8; kc++) {
        const int kb = kc * 8;
        af[kc][0] = __float_as_uint(Qt[(rB + g    ) * KS_STR + kb + tig    ]);
        af[kc][1] = __float_as_uint(Qt[(rB + g + 8) * KS_STR + kb + tig    ]);
        af[kc][2] = __float_as_uint(Qt[(rB + g    ) * KS_STR + kb + tig + 4]);
        af[kc][3] = __float_as_uint(Qt[(rB + g + 8) * KS_STR + kb + tig + 4]);
    }

    {
        const float* Bt = wn ? rpwT : rphT;
        float*       Dt = wn ? Tw   : Th;
#pragma unroll
        for (int nt = 0; nt < 4; nt++) {
            float acc[4] = {0.f, 0.f, 0.f, 0.f};
            const int col = nt * 8 + g;
#pragma unroll
            for (int kc = 0; kc < 8; kc++) {
                const int kb = kc * 8;
                uint32_t bf[2];
                bf[0] = __float_as_uint(Bt[(kb + tig    ) * T_STR + col]);
                bf[1] = __float_as_uint(Bt[(kb + tig + 4) * T_STR + col]);
                mma_tf32(acc, af[kc], bf);
            }
            const int c0 = nt * 8 + 2 * tig;
            Dt[(rB + g    ) * T_STR + c0    ] = acc[0];
            Dt[(rB + g    ) * T_STR + c0 + 1] = acc[1];
            Dt[(rB + g + 8) * T_STR + c0    ] = acc[2];
            Dt[(rB + g + 8) * T_STR + c0 + 1] = acc[3];
        }
    }
    __syncthreads();

    const int r0 = rB + g;
    const int r1 = r0 + 8;
    const int qh0 = qhw[r0],      qw0 = qhw[64 + r0];
    const int qh1 = qhw[r1],      qw1 = qhw[64 + r1];
    float lg[13][4];
#pragma unroll
    for (int it = 0; it < 13; it++) {
        const int nt  = wn * 13 + it;
        float acc[4] = {0.f, 0.f, 0.f, 0.f};
        const int col = nt * 8 + g;
#pragma unroll
        for (int kc = 0; kc < 8; kc++) {
            const int kb = kc * 8;
            uint32_t bf[2];
            bf[0] = __float_as_uint(Ks[col * KS_STR + kb + tig    ]);
            bf[1] = __float_as_uint(Ks[col * KS_STR + kb + tig + 4]);
            mma_tf32(acc, af[kc], bf);
        }
        const int c0 = nt * 8 + 2 * tig;
        const int c1 = c0 + 1;
        if (c0 < HW) {
            int kh = c0 / S_DIM, kw = c0 % S_DIM;
            lg[it][0] = acc[0] * scale + Th[r0 * T_STR + qh0 - kh + 13] + Tw[r0 * T_STR + qw0 - kw + 13];
            lg[it][2] = acc[2] * scale + Th[r1 * T_STR + qh1 - kh + 13] + Tw[r1 * T_STR + qw1 - kw + 13];
        } else { lg[it][0] = -1e30f; lg[it][2] = -1e30f; }
        if (c1 < HW) {
            int kh = c1 / S_DIM, kw = c1 % S_DIM;
            lg[it][1] = acc[1] * scale + Th[r0 * T_STR + qh0 - kh + 13] + Tw[r0 * T_STR + qw0 - kw + 13];
            lg[it][3] = acc[3] * scale + Th[r1 * T_STR + qh1 - kh + 13] + Tw[r1 * T_STR + qw1 - kw + 13];
        } else { lg[it][1] = -1e30f; lg[it][3] = -1e30f; }
    }

    float m0 = -1e30f, m1 = -1e30f;
#pragma unroll
    for (int it = 0; it < 13; it++) {
        m0 = fmaxf(m0, fmaxf(lg[it][0], lg[it][1]));
        m1 = fmaxf(m1, fmaxf(lg[it][2], lg[it][3]));
    }
    m0 = fmaxf(m0, __shfl_xor_sync(0xffffffffu, m0, 1));
    m0 = fmaxf(m0, __shfl_xor_sync(0xffffffffu, m0, 2));
    m1 = fmaxf(m1, __shfl_xor_sync(0xffffffffu, m1, 1));
    m1 = fmaxf(m1, __shfl_xor_sync(0xffffffffu, m1, 2));
    if (tig == 0) { redA[wn * 64 + r0] = m0; redA[wn * 64 + r1] = m1; }
    __syncthreads();
    const float M0 = fmaxf(redA[r0], redA[64 + r0]);
    const float M1 = fmaxf(redA[r1], redA[64 + r1]);

    float s0 = 0.f, s1 = 0.f;
#pragma unroll
    for (int it = 0; it < 13; it++) {
        float e0 = __expf(lg[it][0] - M0); lg[it][0] = e0; s0 += e0;
        float e1 = __expf(lg[it][1] - M0); lg[it][1] = e1; s0 += e1;
        float e2 = __expf(lg[it][2] - M1); lg[it][2] = e2; s1 += e2;
        float e3 = __expf(lg[it][3] - M1); lg[it][3] = e3; s1 += e3;
    }
    s0 += __shfl_xor_sync(0xffffffffu, s0, 1);
    s0 += __shfl_xor_sync(0xffffffffu, s0, 2);
    s1 += __shfl_xor_sync(0xffffffffu, s1, 1);
    s1 += __shfl_xor_sync(0xffffffffu, s1, 2);
    if (tig == 0) { redB[wn * 64 + r0] = s0; redB[wn * 64 + r1] = s1; }
    __syncthreads();
    const float inv0 = 1.0f / (redB[r0] + redB[64 + r0]);
    const float inv1 = 1.0f / (redB[r1] + redB[64 + r1]);

    const int row0 = qbase + r0;
    const int row1 = qbase + r1;
    float* atr0 = at_g + ((size_t)bh * HW + row0) * 200;
    float* atr1 = at_g + ((size_t)bh * HW + row1) * 200;
#pragma unroll
    for (int it = 0; it < 13; it++) {
        const int nt = wn * 13 + it;
        const int c0 = nt * 8 + 2 * tig;
        if (c0 < HW) {
            if (row0 < HW) {
                float2 p = make_float2(f2tf32(lg[it][0] * inv0), f2tf32(lg[it][1] * inv0));
                *(float2*)(atr0 + c0) = p;
            }
            if (row1 < HW) {
                float2 p = make_float2(f2tf32(lg[it][2] * inv1), f2tf32(lg[it][3] * inv1));
                *(float2*)(atr1 + c0) = p;
            }
        }
    }
}

// ---------------------------------------------------------------------------
// Kernel V: out = probs @ V. (unchanged from R5)
// ---------------------------------------------------------------------------
#define V_STR  72
#define AT_STR 204
#define V_SMEM_FLOATS (200 * V_STR + 64 * AT_STR)
#define V_SMEM_BYTES  (V_SMEM_FLOATS * 4)

__global__ __launch_bounds__(256, 2)
void attn_av_kernel(const float* __restrict__ qkv,
                    const float* __restrict__ at_g,
                    float* __restrict__ ctx) {
    extern __shared__ float sm[];
    float* Vs  = sm;
    float* atS = sm + 200 * V_STR;

    const int bh   = blockIdx.x;
    const int b    = bh / NH;
    const int h    = bh % NH;
    const int tid  = threadIdx.x;
    const int warp = tid >> 5;
    const int lane = tid & 31;
    const int g    = lane >> 2;
    const int tig  = lane & 3;
    const int wm   = warp >> 1;
    const int wn   = warp & 1;

    const float* qkv_b = qkv + (size_t)b * HW * QKV_N;
    const float* at_b  = at_g + (size_t)bh * HW * 200;

    for (int slot = tid; slot < 200 * 16; slot += 256) {
        int s  = slot >> 4;
        int d4 = (slot & 15) << 2;
        float4 v = make_float4(0.f, 0.f, 0.f, 0.f);
        if (s < HW) {
            v = *(const float4*)(qkv_b + (size_t)s * QKV_N + 2 * C_DIM + h * HD + d4);
            v.x = f2tf32(v.x); v.y = f2tf32(v.y); v.z = f2tf32(v.z); v.w = f2tf32(v.w);
        }
        *(float4*)&Vs[s * V_STR + d4] = v;
    }

    for (int qb = 0; qb < 4; qb++) {
        const int qbase = qb * 64;
        __syncthreads();

        for (int slot = tid; slot < 64 * 50; slot += 256) {
            int rr = slot / 50;
            int c4 = slot % 50;
            int s  = qbase + rr;
            float4 v = make_float4(0.f, 0.f, 0.f, 0.f);
            if (s < HW && c4 < 49)
                v = *(const float4*)(at_b + (size_t)s * 200 + c4 * 4);
            *(float4*)&atS[rr * AT_STR + c4 * 4] = v;
        }
        __syncthreads();

        const int rB = wm * 16;
        float acc[4][4];
#pragma unroll
        for (int nt = 0; nt < 4; nt++)
#pragma unroll
            for (int i = 0; i < 4; i++) acc[nt][i] = 0.f;

        for (int kc = 0; kc < 25; kc++) {
            const int kb = kc * 8;
            uint32_t a[4];
            a[0] = __float_as_uint(atS[(rB + g    ) * AT_STR + kb + tig    ]);
            a[1] = __float_as_uint(atS[(rB + g + 8) * AT_STR + kb + tig    ]);
            a[2] = __float_as_uint(atS[(rB + g    ) * AT_STR + kb + tig + 4]);
            a[3] = __float_as_uint(atS[(rB + g + 8) * AT_STR + kb + tig + 4]);
#pragma unroll
            for (int nt = 0; nt < 4; nt++) {
                const int col = wn * 32 + nt * 8 + g;
                uint32_t bf[2];
                bf[0] = __float_as_uint(Vs[(kb + tig    ) * V_STR + col]);
                bf[1] = __float_as_uint(Vs[(kb + tig + 4) * V_STR + col]);
                mma_tf32(acc[nt], a, bf);
            }
        }

        const int s0 = qbase + rB + g;
        const int s1 = s0 + 8;
#pragma unroll
        for (int nt = 0; nt < 4; nt++) {
            const int d = wn * 32 + nt * 8 + 2 * tig;
            if (s0 < HW) {
                float2 r0 = make_float2(acc[nt][0], acc[nt][1]);
                *(float2*)(ctx + (size_t)(b * HW + s0) * C_DIM + h * HD + d) = r0;
            }
            if (s1 < HW) {
                float2 r1 = make_float2(acc[nt][2], acc[nt][3]);
                *(float2*)(ctx + (size_t)(b * HW + s1) * C_DIM + h * HD + d) = r1;
            }
        }
    }
}

// ---------------------------------------------------------------------------
extern "C" void kernel_launch(void* const* d_in, const int* in_sizes, int n_in,
                              void* d_out, int out_size) {
    const float* x      = (const float*)d_in[0];
    const float* w_qkv  = (const float*)d_in[1];
    const float* b_qkv  = (const float*)d_in[2];
    const float* w_proj = (const float*)d_in[3];
    const float* b_proj = (const float*)d_in[4];
    const float* rph    = (const float*)d_in[5];
    const float* rpw    = (const float*)d_in[6];
    float* out = (float*)d_out;

    float *qkv_ptr = nullptr, *ctx_ptr = nullptr, *at_ptr = nullptr;
    cudaGetSymbolAddress((void**)&qkv_ptr, g_qkv);
    cudaGetSymbolAddress((void**)&ctx_ptr, g_ctx);
    cudaGetSymbolAddress((void**)&at_ptr, g_at);

    static bool attr_set = false;
    if (!attr_set) {
        cudaFuncSetAttribute(gemm_tf32_bias,
                             cudaFuncAttributeMaxDynamicSharedMemorySize,
                             G_SMEM_BYTES);
        cudaFuncSetAttribute(attn_logits_kernel,
                             cudaFuncAttributeMaxDynamicSharedMemorySize,
                             L_SMEM_BYTES);
        cudaFuncSetAttribute(attn_av_kernel,
                             cudaFuncAttributeMaxDynamicSharedMemorySize,
                             V_SMEM_BYTES);
        attr_set = true;
    }

    // 1) QKV projection (tf32 tensor core, cp.async double-buffered)
    {
        dim3 grid(QKV_N / BN, (M_TOK + BM - 1) / BM);
        gemm_tf32_bias<<<grid, 256, G_SMEM_BYTES>>>(x, w_qkv, b_qkv, qkv_ptr,
                                                    M_TOK, QKV_N, C_DIM);
    }

    // 2a) Logits + bias + softmax -> probs
    attn_logits_kernel<<<NHEADS_TOT * 4, 256, L_SMEM_BYTES>>>(qkv_ptr, rph, rpw, at_ptr);

    // 2b) AV
    attn_av_kernel<<<NHEADS_TOT, 256, V_SMEM_BYTES>>>(qkv_ptr, at_ptr, ctx_ptr);

    // 3) Output projection (tf32 tensor core, cp.async double-buffered)
    {
        dim3 grid(C_DIM / BN, (M_TOK + BM - 1) / BM);
        gemm_tf32_bias<<<grid, 256, G_SMEM_BYTES>>>(ctx_ptr, w_proj, b_proj, out,
                                                    M_TOK, C_DIM, C_DIM);
    }
}